// round 8
// baseline (speedup 1.0000x reference)
#include <cuda_runtime.h>
#include <math.h>
#include <stdint.h>

// Problem constants
#define DMODEL 512
#define NHEADS 8
#define HDIM   64
#define NEXP   8
#define DFF    1024
#define BATCH  8
#define NCHUNK 256
#define NTOT   768            // 3 * 256
#define TOK    (BATCH * NTOT) // 6144
#define SLOTS  (TOK * 2)      // 12288 routed (token, slot) rows

// ---------------- scratch ----------------------------------------------------
__device__ float g_h_hi [TOK * DMODEL];  // LN1 out, tf32 hi/lo
__device__ float g_h_lo [TOK * DMODEL];
__device__ float g_q  [TOK * DMODEL];    // [bh][n][hd]
__device__ float g_k  [TOK * DMODEL];
__device__ float g_v  [TOK * DMODEL];
__device__ float g_o_hi [TOK * DMODEL];  // attn out, tf32 hi/lo
__device__ float g_o_lo [TOK * DMODEL];
__device__ float g_x2 [TOK * DMODEL];    // 2*(o@proj + b)
__device__ float g_hn_hi[TOK * DMODEL];  // LN2 out, tf32 hi/lo
__device__ float g_hn_lo[TOK * DMODEL];
__device__ float g_hid_hi[SLOTS * DFF];  // gelu(...), tf32 hi/lo
__device__ float g_hid_lo[SLOTS * DFF];
__device__ float g_comb[SLOTS * DMODEL]; // conf * (hid @ w2 + b2)
__device__ int   g_rows[NEXP * SLOTS];
__device__ int   g_cnt [NEXP];
__device__ float g_conf[SLOTS];

// pre-split weights (hi/lo tf32)
__device__ float s_qkvw_hi[512 * 1536], s_qkvw_lo[512 * 1536];
__device__ float s_pw_hi  [512 * 512],  s_pw_lo  [512 * 512];
__device__ float s_w1_hi  [NEXP * 512 * 1024], s_w1_lo[NEXP * 512 * 1024];
__device__ float s_w2_hi  [NEXP * 1024 * 512], s_w2_lo[NEXP * 1024 * 512];

// ---------------- helpers ----------------------------------------------------
__device__ __forceinline__ void blockReduce2(float& a, float& b, float* sm) {
    #pragma unroll
    for (int o = 16; o; o >>= 1) {
        a += __shfl_down_sync(0xffffffffu, a, o);
        b += __shfl_down_sync(0xffffffffu, b, o);
    }
    int w = threadIdx.x >> 5, l = threadIdx.x & 31;
    int nw = blockDim.x >> 5;
    if (l == 0) { sm[w] = a; sm[w + 32] = b; }
    __syncthreads();
    if (w == 0) {
        a = (l < nw) ? sm[l] : 0.f;
        b = (l < nw) ? sm[l + 32] : 0.f;
        #pragma unroll
        for (int o = 16; o; o >>= 1) {
            a += __shfl_down_sync(0xffffffffu, a, o);
            b += __shfl_down_sync(0xffffffffu, b, o);
        }
    }
}

__device__ __forceinline__ uint32_t f2tf32(float f) {
    uint32_t r;
    asm("cvt.rna.tf32.f32 %0, %1;" : "=r"(r) : "f"(f));
    return r;
}

__device__ __forceinline__ void store_split(float* hi, float* lo, size_t idx, float x) {
    uint32_t h = f2tf32(x);
    hi[idx] = __uint_as_float(h);
    lo[idx] = __uint_as_float(f2tf32(x - __uint_as_float(h)));
}

__device__ __forceinline__ void mma_tf32(float* c, const uint32_t* a,
                                         const uint32_t* b) {
    asm volatile(
        "mma.sync.aligned.m16n8k8.row.col.f32.tf32.tf32.f32 "
        "{%0,%1,%2,%3}, {%4,%5,%6,%7}, {%8,%9}, {%0,%1,%2,%3};"
        : "+f"(c[0]), "+f"(c[1]), "+f"(c[2]), "+f"(c[3])
        : "r"(a[0]), "r"(a[1]), "r"(a[2]), "r"(a[3]), "r"(b[0]), "r"(b[1]));
}

__device__ __forceinline__ void cp_async16(float* dst, const float* src, bool valid) {
    uint32_t d = (uint32_t)__cvta_generic_to_shared(dst);
    int sz = valid ? 16 : 0;
    asm volatile("cp.async.cg.shared.global [%0], [%1], 16, %2;\n"
                 :: "r"(d), "l"(src), "r"(sz));
}
__device__ __forceinline__ void cp_commit() {
    asm volatile("cp.async.commit_group;\n");
}
template <int N>
__device__ __forceinline__ void cp_wait() {
    asm volatile("cp.async.wait_group %0;\n" :: "n"(N));
}

// ---------------- K0: weight pre-split (hi/lo tf32) --------------------------
#define QKV4 (512 * 1536 / 4)
#define PW4  (512 * 512 / 4)
#define W14  (NEXP * 512 * 1024 / 4)
#define W24  (NEXP * 1024 * 512 / 4)
#define NSPLIT4 (QKV4 + PW4 + W14 + W24)

__global__ void __launch_bounds__(256) k_split_w(
    const float* __restrict__ qw, const float* __restrict__ kvw,
    const float* __restrict__ pw, const float* __restrict__ w1,
    const float* __restrict__ w2)
{
    size_t i4 = (size_t)blockIdx.x * 256 + threadIdx.x;
    if (i4 >= NSPLIT4) return;
    float4 v; float *hid, *lod; size_t off;
    if (i4 < QKV4) {
        size_t row = i4 / 384; int cw = (int)(i4 % 384) * 4;
        v = (cw < 512) ? *(const float4*)(qw + row * 512 + cw)
                       : *(const float4*)(kvw + row * 1024 + (cw - 512));
        hid = s_qkvw_hi; lod = s_qkvw_lo; off = i4 * 4;
    } else if (i4 < QKV4 + PW4) {
        size_t j = i4 - QKV4;
        v = *(const float4*)(pw + j * 4);
        hid = s_pw_hi; lod = s_pw_lo; off = j * 4;
    } else if (i4 < QKV4 + PW4 + W14) {
        size_t j = i4 - QKV4 - PW4;
        v = *(const float4*)(w1 + j * 4);
        hid = s_w1_hi; lod = s_w1_lo; off = j * 4;
    } else {
        size_t j = i4 - QKV4 - PW4 - W14;
        v = *(const float4*)(w2 + j * 4);
        hid = s_w2_hi; lod = s_w2_lo; off = j * 4;
    }
    store_split(hid, lod, off + 0, v.x);
    store_split(hid, lod, off + 1, v.y);
    store_split(hid, lod, off + 2, v.z);
    store_split(hid, lod, off + 3, v.w);
}

// ---------------- K1: LN1 on concat(x1,x2,x3); zero routing counters --------
__global__ void __launch_bounds__(256) k_ln1(
    const float* __restrict__ x1, const float* __restrict__ x2,
    const float* __restrict__ x3,
    const float* __restrict__ w, const float* __restrict__ b)
{
    int t = blockIdx.x, tid = threadIdx.x;
    if (t == 0 && tid < NEXP) g_cnt[tid] = 0;
    int bb = t / NTOT, pos = t % NTOT;
    const float* src = (pos < NCHUNK) ? x1 : (pos < 2 * NCHUNK) ? x2 : x3;
    const float* row = src + ((size_t)bb * NCHUNK + (pos % NCHUNK)) * DMODEL;
    float v0 = row[tid], v1 = row[tid + 256];
    float s = v0 + v1, ss = v0 * v0 + v1 * v1;
    __shared__ float red[64];
    blockReduce2(s, ss, red);
    __shared__ float mu, rstd;
    if (tid == 0) {
        float m = s * (1.f / 512.f);
        float var = ss * (1.f / 512.f) - m * m;
        mu = m; rstd = rsqrtf(var + 1e-5f);
    }
    __syncthreads();
    size_t base = (size_t)t * DMODEL;
    store_split(g_h_hi, g_h_lo, base + tid,
                (v0 - mu) * rstd * w[tid] + b[tid]);
    store_split(g_h_hi, g_h_lo, base + tid + 256,
                (v1 - mu) * rstd * w[tid + 256] + b[tid + 256]);
}

// ---------------- pre-split 3xTF32 pipelined 128x128x8 GEMM -----------------
// 256 threads = 8 warps, warp grid 2(M) x 4(N), warp tile 64x32.
// Operands already hi/lo tf32 in global; pure cp.async + LDS + MMA loop.
#define AP2 12            // A smem row stride (8 k + 4 pad)
#define BPW 136           // B smem row stride (128 n + 8 pad)
#define AH_SZ (128 * AP2)
#define BH_SZ (8 * BPW)

__device__ __forceinline__ void gemm_pre(
    const float* __restrict__ Ahg, const float* __restrict__ Alg, int lda,
    const int* __restrict__ arow_s,
    const float* __restrict__ Bhg, const float* __restrict__ Blg, int ldb,
    int Kdim, float (&acc)[4][4][4],
    float* sAh, float* sAl, float* sBh, float* sBl)
{
    const int tid  = threadIdx.x;
    const int warp = tid >> 5, lane = tid & 31;
    const int gid  = lane >> 2, tig = lane & 3;
    const int wm   = (warp & 1) * 64;
    const int wn   = (warp >> 1) * 32;

    // producer coords: A 128x8 per comp = 256 float4; B 8x128 = 256 float4
    const int a_r = tid & 127, a_c = (tid >> 7) * 4;
    const int b_r = tid >> 5,  b_c = (tid & 31) * 4;
    const int ga  = arow_s[a_r];
    const bool av = ga >= 0;
    const float* Ahp = Ahg + (size_t)(av ? ga : 0) * lda + a_c;
    const float* Alp = Alg + (size_t)(av ? ga : 0) * lda + a_c;

    auto load = [&](int k0, int buf) {
        cp_async16(sAh + buf * AH_SZ + a_r * AP2 + a_c, Ahp + k0, av);
        cp_async16(sAl + buf * AH_SZ + a_r * AP2 + a_c, Alp + k0, av);
        cp_async16(sBh + buf * BH_SZ + b_r * BPW + b_c,
                   Bhg + (size_t)(k0 + b_r) * ldb + b_c, true);
        cp_async16(sBl + buf * BH_SZ + b_r * BPW + b_c,
                   Blg + (size_t)(k0 + b_r) * ldb + b_c, true);
    };

    const int nk = Kdim >> 3;
    load(0, 0);
    cp_commit();

    for (int it = 0; it < nk; it++) {
        if (it + 1 < nk) load((it + 1) << 3, (it + 1) & 1);
        cp_commit();
        cp_wait<1>();
        __syncthreads();

        const float* fAh = sAh + (it & 1) * AH_SZ;
        const float* fAl = sAl + (it & 1) * AH_SZ;
        const float* fBh = sBh + (it & 1) * BH_SZ;
        const float* fBl = sBl + (it & 1) * BH_SZ;

        uint32_t ah[4][4], al[4][4], bh[4][2], bl[4][2];
        #pragma unroll
        for (int i = 0; i < 4; i++) {
            int off = (wm + i * 16 + gid) * AP2 + tig;
            ah[i][0] = __float_as_uint(fAh[off]);
            ah[i][1] = __float_as_uint(fAh[off + 8 * AP2]);
            ah[i][2] = __float_as_uint(fAh[off + 4]);
            ah[i][3] = __float_as_uint(fAh[off + 8 * AP2 + 4]);
            al[i][0] = __float_as_uint(fAl[off]);
            al[i][1] = __float_as_uint(fAl[off + 8 * AP2]);
            al[i][2] = __float_as_uint(fAl[off + 4]);
            al[i][3] = __float_as_uint(fAl[off + 8 * AP2 + 4]);
        }
        #pragma unroll
        for (int j = 0; j < 4; j++) {
            int off = tig * BPW + wn + j * 8 + gid;
            bh[j][0] = __float_as_uint(fBh[off]);
            bh[j][1] = __float_as_uint(fBh[off + 4 * BPW]);
            bl[j][0] = __float_as_uint(fBl[off]);
            bl[j][1] = __float_as_uint(fBl[off + 4 * BPW]);
        }
        #pragma unroll
        for (int i = 0; i < 4; i++)
            #pragma unroll
            for (int j = 0; j < 4; j++) {
                mma_tf32(acc[i][j], al[i], bh[j]);  // lo*hi
                mma_tf32(acc[i][j], ah[i], bl[j]);  // hi*lo
                mma_tf32(acc[i][j], ah[i], bh[j]);  // hi*hi
            }
        __syncthreads();
    }
}

// Epilogue fragment coords: rows r0=wm+i*16+gid, r1=r0+8;
// cols c0=wn+j*8+tig*2, c0+1. regs: [0]=(r0,c0) [1]=(r0,c0+1) [2]=(r1,c0) [3]=(r1,c0+1)

// ---------------- K2: QKV GEMM (h @ qkvw_combined) --------------------------
__global__ void __launch_bounds__(256) k_qkv()
{
    __shared__ float sAh[2 * AH_SZ], sAl[2 * AH_SZ], sBh[2 * BH_SZ], sBl[2 * BH_SZ];
    __shared__ int arow[128];
    int bx = blockIdx.x;  // 0..11 (col tile of 1536)
    int by = blockIdx.y;  // 0..47
    int tid = threadIdx.x;
    if (tid < 128) arow[tid] = by * 128 + tid;
    __syncthreads();

    float acc[4][4][4] = {};
    gemm_pre(g_h_hi, g_h_lo, DMODEL, arow,
             s_qkvw_hi + bx * 128, s_qkvw_lo + bx * 128, 1536, DMODEL,
             acc, sAh, sAl, sBh, sBl);

    int warp = tid >> 5, lane = tid & 31, gid = lane >> 2, tig = lane & 3;
    int wm = (warp & 1) * 64, wn = (warp >> 1) * 32;
    #pragma unroll
    for (int i = 0; i < 4; i++) {
        #pragma unroll
        for (int j = 0; j < 4; j++) {
            #pragma unroll
            for (int rg = 0; rg < 4; rg++) {
                int r = wm + i * 16 + gid + (rg >> 1) * 8;
                int c = wn + j * 8 + tig * 2 + (rg & 1);
                int gr = by * 128 + r;
                int gc = bx * 128 + c;
                int bb = gr / NTOT, n = gr % NTOT;
                int which = gc >> 9;
                int cc = gc & 511;
                int h = cc >> 6, hd = cc & 63;
                float* dst = (which == 0) ? g_q : (which == 1) ? g_k : g_v;
                dst[(((size_t)bb * NHEADS + h) * NTOT + n) * HDIM + hd] = acc[i][j][rg];
            }
        }
    }
}

// ---------------- K3: attention (flash-style, 1 query row / thread) ---------
__global__ void __launch_bounds__(128) k_attn()
{
    int bh = blockIdx.x;                       // 64
    int n  = blockIdx.y * 128 + threadIdx.x;   // query row
    const float* qp = g_q + ((size_t)bh * NTOT + n) * HDIM;
    float q[HDIM];
    #pragma unroll
    for (int i = 0; i < HDIM; i += 4) {
        float4 t4 = *(const float4*)(qp + i);
        q[i] = t4.x * 0.125f; q[i+1] = t4.y * 0.125f;
        q[i+2] = t4.z * 0.125f; q[i+3] = t4.w * 0.125f;
    }
    float acc[HDIM];
    #pragma unroll
    for (int i = 0; i < HDIM; i++) acc[i] = 0.f;
    float m = -1e30f, l = 0.f;

    __shared__ float Ks[32 * 64], Vs[32 * 64];
    const float* kb = g_k + (size_t)bh * NTOT * HDIM;
    const float* vb = g_v + (size_t)bh * NTOT * HDIM;

    for (int c = 0; c < NTOT; c += 32) {
        __syncthreads();
        #pragma unroll
        for (int i = threadIdx.x; i < 512; i += 128) {
            *(float4*)(Ks + i * 4) = *(const float4*)(kb + c * 64 + i * 4);
            *(float4*)(Vs + i * 4) = *(const float4*)(vb + c * 64 + i * 4);
        }
        __syncthreads();

        float s[32];
        #pragma unroll
        for (int j = 0; j < 32; j++) {
            float d0 = 0.f;
            #pragma unroll
            for (int d = 0; d < 64; d += 4) {
                float4 kk = *(const float4*)(Ks + j * 64 + d);
                d0 += q[d] * kk.x + q[d+1] * kk.y + q[d+2] * kk.z + q[d+3] * kk.w;
            }
            s[j] = d0;
        }
        float cm = s[0];
        #pragma unroll
        for (int j = 1; j < 32; j++) cm = fmaxf(cm, s[j]);
        float mn = fmaxf(m, cm);
        float f = __expf(m - mn);
        m = mn;
        l *= f;
        #pragma unroll
        for (int d = 0; d < 64; d++) acc[d] *= f;
        #pragma unroll
        for (int j = 0; j < 32; j++) {
            float p = __expf(s[j] - m);
            l += p;
            #pragma unroll
            for (int d = 0; d < 64; d += 4) {
                float4 vv = *(const float4*)(Vs + j * 64 + d);
                acc[d]   += p * vv.x; acc[d+1] += p * vv.y;
                acc[d+2] += p * vv.z; acc[d+3] += p * vv.w;
            }
        }
    }
    float inv = 1.f / l;
    int bb = bh >> 3, h = bh & 7;
    size_t base = ((size_t)bb * NTOT + n) * DMODEL + h * HDIM;
    #pragma unroll
    for (int d = 0; d < 64; d++)
        store_split(g_o_hi, g_o_lo, base + d, acc[d] * inv);
}

// ---------------- K4: proj GEMM, x2 = 2*(o @ proj_w + proj_b) ---------------
__global__ void __launch_bounds__(256) k_proj(const float* __restrict__ pb)
{
    __shared__ float sAh[2 * AH_SZ], sAl[2 * AH_SZ], sBh[2 * BH_SZ], sBl[2 * BH_SZ];
    __shared__ int arow[128];
    int bx = blockIdx.x, by = blockIdx.y;
    int tid = threadIdx.x;
    if (tid < 128) arow[tid] = by * 128 + tid;
    __syncthreads();

    float acc[4][4][4] = {};
    gemm_pre(g_o_hi, g_o_lo, DMODEL, arow,
             s_pw_hi + bx * 128, s_pw_lo + bx * 128, DMODEL, DMODEL,
             acc, sAh, sAl, sBh, sBl);

    int warp = tid >> 5, lane = tid & 31, gid = lane >> 2, tig = lane & 3;
    int wm = (warp & 1) * 64, wn = (warp >> 1) * 32;
    #pragma unroll
    for (int i = 0; i < 4; i++) {
        #pragma unroll
        for (int j = 0; j < 4; j++) {
            #pragma unroll
            for (int rg = 0; rg < 4; rg++) {
                int r = wm + i * 16 + gid + (rg >> 1) * 8;
                int c = wn + j * 8 + tig * 2 + (rg & 1);
                int gr = by * 128 + r;
                int gc = bx * 128 + c;
                g_x2[(size_t)gr * DMODEL + gc] = 2.f * (acc[i][j][rg] + pb[gc]);
            }
        }
    }
}

// ---------------- K5: LN2 + gate softmax + top2 routing ---------------------
__global__ void __launch_bounds__(128) k_gate(
    const float* __restrict__ n2w, const float* __restrict__ n2b,
    const float* __restrict__ gw)
{
    int t = blockIdx.x, tid = threadIdx.x;
    __shared__ float hs[DMODEL];
    __shared__ float red[64];
    const float* xr = g_x2 + (size_t)t * DMODEL;
    float v[4]; float s = 0.f, ss = 0.f;
    #pragma unroll
    for (int i = 0; i < 4; i++) {
        v[i] = xr[tid + i * 128];
        s += v[i]; ss += v[i] * v[i];
    }
    blockReduce2(s, ss, red);
    __shared__ float mu, rstd;
    if (tid == 0) {
        float m = s * (1.f / 512.f);
        mu = m; rstd = rsqrtf(ss * (1.f / 512.f) - m * m + 1e-5f);
    }
    __syncthreads();
    #pragma unroll
    for (int i = 0; i < 4; i++) {
        int d = tid + i * 128;
        float hv = (v[i] - mu) * rstd * n2w[d] + n2b[d];
        hs[d] = hv;
        store_split(g_hn_hi, g_hn_lo, (size_t)t * DMODEL + d, hv);
    }
    __syncthreads();
    int e = tid >> 4, ln = tid & 15;
    float p = 0.f;
    for (int d = ln; d < DMODEL; d += 16) p += hs[d] * gw[d * NEXP + e];
    #pragma unroll
    for (int o = 8; o; o >>= 1) p += __shfl_down_sync(0xffffffffu, p, o, 16);
    __shared__ float lg[NEXP];
    if (ln == 0) lg[e] = p;
    __syncthreads();
    if (tid == 0) {
        int i0 = 0; float b0 = lg[0];
        #pragma unroll
        for (int i = 1; i < NEXP; i++) if (lg[i] > b0) { b0 = lg[i]; i0 = i; }
        int i1 = -1; float b1 = -1e30f;
        #pragma unroll
        for (int i = 0; i < NEXP; i++) {
            if (i == i0) continue;
            if (lg[i] > b1) { b1 = lg[i]; i1 = i; }
        }
        float c0 = 1.f / (1.f + __expf(b1 - b0));
        int p0 = atomicAdd(&g_cnt[i0], 1);
        g_rows[i0 * SLOTS + p0] = t * 2;
        int p1 = atomicAdd(&g_cnt[i1], 1);
        g_rows[i1 * SLOTS + p1] = t * 2 + 1;
        g_conf[t * 2] = c0;
        g_conf[t * 2 + 1] = 1.f - c0;
    }
}

// ---------------- K6: grouped MoE GEMM 1 (hn @ w1, gelu) --------------------
__global__ void __launch_bounds__(256) k_moe1(const float* __restrict__ b1)
{
    int e = blockIdx.z, by = blockIdx.y, bx = blockIdx.x;
    int cnt = g_cnt[e];
    if (by * 128 >= cnt) return;
    __shared__ float sAh[2 * AH_SZ], sAl[2 * AH_SZ], sBh[2 * BH_SZ], sBl[2 * BH_SZ];
    __shared__ int arow[128], ent_s[128];
    int tid = threadIdx.x;
    if (tid < 128) {
        int rr = by * 128 + tid;
        int ent = (rr < cnt) ? g_rows[e * SLOTS + rr] : -1;
        ent_s[tid] = ent;
        arow[tid] = (ent >= 0) ? (ent >> 1) : -1;
    }
    __syncthreads();

    float acc[4][4][4] = {};
    gemm_pre(g_hn_hi, g_hn_lo, DMODEL, arow,
             s_w1_hi + (size_t)e * 512 * 1024 + bx * 128,
             s_w1_lo + (size_t)e * 512 * 1024 + bx * 128, DFF, DMODEL,
             acc, sAh, sAl, sBh, sBl);

    int warp = tid >> 5, lane = tid & 31, gid = lane >> 2, tig = lane & 3;
    int wm = (warp & 1) * 64, wn = (warp >> 1) * 32;
    #pragma unroll
    for (int i = 0; i < 4; i++) {
        #pragma unroll
        for (int j = 0; j < 4; j++) {
            #pragma unroll
            for (int rg = 0; rg < 4; rg++) {
                int r = wm + i * 16 + gid + (rg >> 1) * 8;
                int ent = ent_s[r];
                if (ent < 0) continue;
                int gc = bx * 128 + wn + j * 8 + tig * 2 + (rg & 1);
                float vv = acc[i][j][rg] + b1[e * DFF + gc];
                vv = 0.5f * vv * (1.f + erff(vv * 0.70710678118654752f));
                store_split(g_hid_hi, g_hid_lo, (size_t)ent * DFF + gc, vv);
            }
        }
    }
}

// ---------------- K7: grouped MoE GEMM 2 (hid @ w2, *conf) ------------------
__global__ void __launch_bounds__(256) k_moe2(const float* __restrict__ b2)
{
    int e = blockIdx.z, by = blockIdx.y, bx = blockIdx.x;
    int cnt = g_cnt[e];
    if (by * 128 >= cnt) return;
    __shared__ float sAh[2 * AH_SZ], sAl[2 * AH_SZ], sBh[2 * BH_SZ], sBl[2 * BH_SZ];
    __shared__ int arow[128], ent_s[128];
    int tid = threadIdx.x;
    if (tid < 128) {
        int rr = by * 128 + tid;
        int ent = (rr < cnt) ? g_rows[e * SLOTS + rr] : -1;
        ent_s[tid] = ent;
        arow[tid] = ent;
    }
    __syncthreads();

    float acc[4][4][4] = {};
    gemm_pre(g_hid_hi, g_hid_lo, DFF, arow,
             s_w2_hi + (size_t)e * 1024 * 512 + bx * 128,
             s_w2_lo + (size_t)e * 1024 * 512 + bx * 128, DMODEL, DFF,
             acc, sAh, sAl, sBh, sBl);

    int warp = tid >> 5, lane = tid & 31, gid = lane >> 2, tig = lane & 3;
    int wm = (warp & 1) * 64, wn = (warp >> 1) * 32;
    #pragma unroll
    for (int i = 0; i < 4; i++) {
        #pragma unroll
        for (int j = 0; j < 4; j++) {
            #pragma unroll
            for (int rg = 0; rg < 4; rg++) {
                int r = wm + i * 16 + gid + (rg >> 1) * 8;
                int ent = ent_s[r];
                if (ent < 0) continue;
                float cf = g_conf[ent];
                int gc = bx * 128 + wn + j * 8 + tig * 2 + (rg & 1);
                g_comb[(size_t)ent * DMODEL + gc] = cf * (acc[i][j][rg] + b2[e * DMODEL + gc]);
            }
        }
    }
}

// ---------------- K8: residual + LN(ln1) → out ------------------------------
__global__ void __launch_bounds__(256) k_final(
    const float* __restrict__ lw, const float* __restrict__ lb,
    float* __restrict__ out)
{
    int t = blockIdx.x, tid = threadIdx.x;
    const float* xr = g_x2 + (size_t)t * DMODEL;
    const float* c0 = g_comb + (size_t)(t * 2) * DMODEL;
    const float* c1 = g_comb + (size_t)(t * 2 + 1) * DMODEL;
    float v0 = xr[tid]       + c0[tid]       + c1[tid];
    float v1 = xr[tid + 256] + c0[tid + 256] + c1[tid + 256];
    float s = v0 + v1, ss = v0 * v0 + v1 * v1;
    __shared__ float red[64];
    blockReduce2(s, ss, red);
    __shared__ float mu, rstd;
    if (tid == 0) {
        float m = s * (1.f / 512.f);
        mu = m; rstd = rsqrtf(ss * (1.f / 512.f) - m * m + 1e-5f);
    }
    __syncthreads();
    out[(size_t)t * DMODEL + tid]       = (v0 - mu) * rstd * lw[tid]       + lb[tid];
    out[(size_t)t * DMODEL + tid + 256] = (v1 - mu) * rstd * lw[tid + 256] + lb[tid + 256];
}

// ---------------- launch -----------------------------------------------------
extern "C" void kernel_launch(void* const* d_in, const int* in_sizes, int n_in,
                              void* d_out, int out_size)
{
    const float* x1   = (const float*)d_in[0];
    const float* x2   = (const float*)d_in[1];
    const float* x3   = (const float*)d_in[2];
    const float* n1w  = (const float*)d_in[3];
    const float* n1b  = (const float*)d_in[4];
    const float* n2w  = (const float*)d_in[5];
    const float* n2b  = (const float*)d_in[6];
    const float* l1w  = (const float*)d_in[7];
    const float* l1b  = (const float*)d_in[8];
    const float* qw   = (const float*)d_in[9];
    const float* kvw  = (const float*)d_in[10];
    const float* pw   = (const float*)d_in[11];
    const float* pb   = (const float*)d_in[12];
    const float* gw   = (const float*)d_in[13];
    const float* ew1  = (const float*)d_in[14];
    const float* eb1  = (const float*)d_in[15];
    const float* ew2  = (const float*)d_in[16];
    const float* ew2b = (const float*)d_in[17];
    float* out = (float*)d_out;

    k_split_w<<<(NSPLIT4 + 255) / 256, 256>>>(qw, kvw, pw, ew1, ew2);
    k_ln1<<<TOK, 256>>>(x1, x2, x3, n1w, n1b);
    { dim3 g(12, 48); k_qkv<<<g, 256>>>(); }
    { dim3 g(64, 6);  k_attn<<<g, 128>>>(); }
    { dim3 g(4, 48);  k_proj<<<g, 256>>>(pb); }
    k_gate<<<TOK, 128>>>(n2w, n2b, gw);
    { dim3 g(8, 96, 8); k_moe1<<<g, 256>>>(eb1); }
    { dim3 g(4, 96, 8); k_moe2<<<g, 256>>>(ew2b); }
    k_final<<<TOK, 256>>>(l1w, l1b, out);
}

// round 9
// speedup vs baseline: 1.0140x; 1.0140x over previous
#include <cuda_runtime.h>
#include <math.h>
#include <stdint.h>

// Problem constants
#define DMODEL 512
#define NHEADS 8
#define HDIM   64
#define NEXP   8
#define DFF    1024
#define BATCH  8
#define NCHUNK 256
#define NTOT   768            // 3 * 256
#define TOK    (BATCH * NTOT) // 6144
#define SLOTS  (TOK * 2)      // 12288 routed (token, slot) rows

// ---------------- scratch ----------------------------------------------------
__device__ float g_h_hi [TOK * DMODEL];  // LN1 out, tf32 hi/lo
__device__ float g_h_lo [TOK * DMODEL];
__device__ float g_q  [TOK * DMODEL];    // [bh][n][hd]
__device__ float g_k  [TOK * DMODEL];
__device__ float g_v  [TOK * DMODEL];
__device__ float g_o    [TOK * DMODEL];  // attn out (plain fp32)
__device__ float g_o_hi [TOK * DMODEL];  // attn out, tf32 hi/lo
__device__ float g_o_lo [TOK * DMODEL];
__device__ float g_x2 [TOK * DMODEL];    // 2*(o@proj + b)
__device__ float g_hn_hi[TOK * DMODEL];  // LN2 out, tf32 hi/lo
__device__ float g_hn_lo[TOK * DMODEL];
__device__ float g_hid_hi[SLOTS * DFF];  // gelu(...), tf32 hi/lo
__device__ float g_hid_lo[SLOTS * DFF];
__device__ float g_comb[SLOTS * DMODEL]; // conf * (hid @ w2 + b2)
__device__ int   g_rows[NEXP * SLOTS];
__device__ int   g_cnt [NEXP];
__device__ float g_conf[SLOTS];

// pre-split weights (hi/lo tf32)
__device__ float s_qkvw_hi[512 * 1536], s_qkvw_lo[512 * 1536];
__device__ float s_pw_hi  [512 * 512],  s_pw_lo  [512 * 512];
__device__ float s_w1_hi  [NEXP * 512 * 1024], s_w1_lo[NEXP * 512 * 1024];
__device__ float s_w2_hi  [NEXP * 1024 * 512], s_w2_lo[NEXP * 1024 * 512];

// ---------------- helpers ----------------------------------------------------
__device__ __forceinline__ void blockReduce2(float& a, float& b, float* sm) {
    #pragma unroll
    for (int o = 16; o; o >>= 1) {
        a += __shfl_down_sync(0xffffffffu, a, o);
        b += __shfl_down_sync(0xffffffffu, b, o);
    }
    int w = threadIdx.x >> 5, l = threadIdx.x & 31;
    int nw = blockDim.x >> 5;
    if (l == 0) { sm[w] = a; sm[w + 32] = b; }
    __syncthreads();
    if (w == 0) {
        a = (l < nw) ? sm[l] : 0.f;
        b = (l < nw) ? sm[l + 32] : 0.f;
        #pragma unroll
        for (int o = 16; o; o >>= 1) {
            a += __shfl_down_sync(0xffffffffu, a, o);
            b += __shfl_down_sync(0xffffffffu, b, o);
        }
    }
}

__device__ __forceinline__ uint32_t f2tf32(float f) {
    uint32_t r;
    asm("cvt.rna.tf32.f32 %0, %1;" : "=r"(r) : "f"(f));
    return r;
}

__device__ __forceinline__ void store_split(float* hi, float* lo, size_t idx, float x) {
    uint32_t h = f2tf32(x);
    hi[idx] = __uint_as_float(h);
    lo[idx] = __uint_as_float(f2tf32(x - __uint_as_float(h)));
}

__device__ __forceinline__ void mma_tf32(float* c, const uint32_t* a,
                                         const uint32_t* b) {
    asm volatile(
        "mma.sync.aligned.m16n8k8.row.col.f32.tf32.tf32.f32 "
        "{%0,%1,%2,%3}, {%4,%5,%6,%7}, {%8,%9}, {%0,%1,%2,%3};"
        : "+f"(c[0]), "+f"(c[1]), "+f"(c[2]), "+f"(c[3])
        : "r"(a[0]), "r"(a[1]), "r"(a[2]), "r"(a[3]), "r"(b[0]), "r"(b[1]));
}

__device__ __forceinline__ void cp_async16(float* dst, const float* src, bool valid) {
    uint32_t d = (uint32_t)__cvta_generic_to_shared(dst);
    int sz = valid ? 16 : 0;
    asm volatile("cp.async.cg.shared.global [%0], [%1], 16, %2;\n"
                 :: "r"(d), "l"(src), "r"(sz));
}
__device__ __forceinline__ void cp_commit() {
    asm volatile("cp.async.commit_group;\n");
}
template <int N>
__device__ __forceinline__ void cp_wait() {
    asm volatile("cp.async.wait_group %0;\n" :: "n"(N));
}

// ---------------- K0: weight pre-split (hi/lo tf32) --------------------------
#define QKV4 (512 * 1536 / 4)
#define PW4  (512 * 512 / 4)
#define W14  (NEXP * 512 * 1024 / 4)
#define W24  (NEXP * 1024 * 512 / 4)
#define NSPLIT4 (QKV4 + PW4 + W14 + W24)

__global__ void __launch_bounds__(256) k_split_w(
    const float* __restrict__ qw, const float* __restrict__ kvw,
    const float* __restrict__ pw, const float* __restrict__ w1,
    const float* __restrict__ w2)
{
    size_t i4 = (size_t)blockIdx.x * 256 + threadIdx.x;
    if (i4 >= NSPLIT4) return;
    float4 v; float *hid, *lod; size_t off;
    if (i4 < QKV4) {
        size_t row = i4 / 384; int cw = (int)(i4 % 384) * 4;
        v = (cw < 512) ? *(const float4*)(qw + row * 512 + cw)
                       : *(const float4*)(kvw + row * 1024 + (cw - 512));
        hid = s_qkvw_hi; lod = s_qkvw_lo; off = i4 * 4;
    } else if (i4 < QKV4 + PW4) {
        size_t j = i4 - QKV4;
        v = *(const float4*)(pw + j * 4);
        hid = s_pw_hi; lod = s_pw_lo; off = j * 4;
    } else if (i4 < QKV4 + PW4 + W14) {
        size_t j = i4 - QKV4 - PW4;
        v = *(const float4*)(w1 + j * 4);
        hid = s_w1_hi; lod = s_w1_lo; off = j * 4;
    } else {
        size_t j = i4 - QKV4 - PW4 - W14;
        v = *(const float4*)(w2 + j * 4);
        hid = s_w2_hi; lod = s_w2_lo; off = j * 4;
    }
    store_split(hid, lod, off + 0, v.x);
    store_split(hid, lod, off + 1, v.y);
    store_split(hid, lod, off + 2, v.z);
    store_split(hid, lod, off + 3, v.w);
}

// ---------------- K0b: split attention output (elementwise) -----------------
__global__ void __launch_bounds__(256) k_split_o()
{
    size_t i4 = (size_t)blockIdx.x * 256 + threadIdx.x;   // TOK*DMODEL/4 quads
    float4 v = *(const float4*)(g_o + i4 * 4);
    store_split(g_o_hi, g_o_lo, i4 * 4 + 0, v.x);
    store_split(g_o_hi, g_o_lo, i4 * 4 + 1, v.y);
    store_split(g_o_hi, g_o_lo, i4 * 4 + 2, v.z);
    store_split(g_o_hi, g_o_lo, i4 * 4 + 3, v.w);
}

// ---------------- K1: LN1 on concat(x1,x2,x3); zero routing counters --------
__global__ void __launch_bounds__(256) k_ln1(
    const float* __restrict__ x1, const float* __restrict__ x2,
    const float* __restrict__ x3,
    const float* __restrict__ w, const float* __restrict__ b)
{
    int t = blockIdx.x, tid = threadIdx.x;
    if (t == 0 && tid < NEXP) g_cnt[tid] = 0;
    int bb = t / NTOT, pos = t % NTOT;
    const float* src = (pos < NCHUNK) ? x1 : (pos < 2 * NCHUNK) ? x2 : x3;
    const float* row = src + ((size_t)bb * NCHUNK + (pos % NCHUNK)) * DMODEL;
    float v0 = row[tid], v1 = row[tid + 256];
    float s = v0 + v1, ss = v0 * v0 + v1 * v1;
    __shared__ float red[64];
    blockReduce2(s, ss, red);
    __shared__ float mu, rstd;
    if (tid == 0) {
        float m = s * (1.f / 512.f);
        float var = ss * (1.f / 512.f) - m * m;
        mu = m; rstd = rsqrtf(var + 1e-5f);
    }
    __syncthreads();
    size_t base = (size_t)t * DMODEL;
    store_split(g_h_hi, g_h_lo, base + tid,
                (v0 - mu) * rstd * w[tid] + b[tid]);
    store_split(g_h_hi, g_h_lo, base + tid + 256,
                (v1 - mu) * rstd * w[tid + 256] + b[tid + 256]);
}

// ---------------- pre-split 3xTF32 pipelined 128x128x8 GEMM -----------------
// 256 threads = 8 warps, warp grid 2(M) x 4(N), warp tile 64x32.
// Operands already hi/lo tf32 in global; pure cp.async + LDS + MMA loop.
#define AP2 12            // A smem row stride (8 k + 4 pad)
#define BPW 136           // B smem row stride (128 n + 8 pad)
#define AH_SZ (128 * AP2)
#define BH_SZ (8 * BPW)

__device__ __forceinline__ void gemm_pre(
    const float* __restrict__ Ahg, const float* __restrict__ Alg, int lda,
    const int* __restrict__ arow_s,
    const float* __restrict__ Bhg, const float* __restrict__ Blg, int ldb,
    int Kdim, float (&acc)[4][4][4],
    float* sAh, float* sAl, float* sBh, float* sBl)
{
    const int tid  = threadIdx.x;
    const int warp = tid >> 5, lane = tid & 31;
    const int gid  = lane >> 2, tig = lane & 3;
    const int wm   = (warp & 1) * 64;
    const int wn   = (warp >> 1) * 32;

    // producer coords: A 128x8 per comp = 256 float4; B 8x128 = 256 float4
    const int a_r = tid & 127, a_c = (tid >> 7) * 4;
    const int b_r = tid >> 5,  b_c = (tid & 31) * 4;
    const int ga  = arow_s[a_r];
    const bool av = ga >= 0;
    const float* Ahp = Ahg + (size_t)(av ? ga : 0) * lda + a_c;
    const float* Alp = Alg + (size_t)(av ? ga : 0) * lda + a_c;

    auto load = [&](int k0, int buf) {
        cp_async16(sAh + buf * AH_SZ + a_r * AP2 + a_c, Ahp + k0, av);
        cp_async16(sAl + buf * AH_SZ + a_r * AP2 + a_c, Alp + k0, av);
        cp_async16(sBh + buf * BH_SZ + b_r * BPW + b_c,
                   Bhg + (size_t)(k0 + b_r) * ldb + b_c, true);
        cp_async16(sBl + buf * BH_SZ + b_r * BPW + b_c,
                   Blg + (size_t)(k0 + b_r) * ldb + b_c, true);
    };

    const int nk = Kdim >> 3;
    load(0, 0);
    cp_commit();

    for (int it = 0; it < nk; it++) {
        if (it + 1 < nk) load((it + 1) << 3, (it + 1) & 1);
        cp_commit();
        cp_wait<1>();
        __syncthreads();

        const float* fAh = sAh + (it & 1) * AH_SZ;
        const float* fAl = sAl + (it & 1) * AH_SZ;
        const float* fBh = sBh + (it & 1) * BH_SZ;
        const float* fBl = sBl + (it & 1) * BH_SZ;

        uint32_t ah[4][4], al[4][4], bh[4][2], bl[4][2];
        #pragma unroll
        for (int i = 0; i < 4; i++) {
            int off = (wm + i * 16 + gid) * AP2 + tig;
            ah[i][0] = __float_as_uint(fAh[off]);
            ah[i][1] = __float_as_uint(fAh[off + 8 * AP2]);
            ah[i][2] = __float_as_uint(fAh[off + 4]);
            ah[i][3] = __float_as_uint(fAh[off + 8 * AP2 + 4]);
            al[i][0] = __float_as_uint(fAl[off]);
            al[i][1] = __float_as_uint(fAl[off + 8 * AP2]);
            al[i][2] = __float_as_uint(fAl[off + 4]);
            al[i][3] = __float_as_uint(fAl[off + 8 * AP2 + 4]);
        }
        #pragma unroll
        for (int j = 0; j < 4; j++) {
            int off = tig * BPW + wn + j * 8 + gid;
            bh[j][0] = __float_as_uint(fBh[off]);
            bh[j][1] = __float_as_uint(fBh[off + 4 * BPW]);
            bl[j][0] = __float_as_uint(fBl[off]);
            bl[j][1] = __float_as_uint(fBl[off + 4 * BPW]);
        }
        #pragma unroll
        for (int i = 0; i < 4; i++)
            #pragma unroll
            for (int j = 0; j < 4; j++) {
                mma_tf32(acc[i][j], al[i], bh[j]);  // lo*hi
                mma_tf32(acc[i][j], ah[i], bl[j]);  // hi*lo
                mma_tf32(acc[i][j], ah[i], bh[j]);  // hi*hi
            }
        __syncthreads();
    }
}

// Epilogue fragment coords: rows r0=wm+i*16+gid, r1=r0+8;
// cols c0=wn+j*8+tig*2, c0+1. regs: [0]=(r0,c0) [1]=(r0,c0+1) [2]=(r1,c0) [3]=(r1,c0+1)

// ---------------- K2: QKV GEMM (h @ qkvw_combined) --------------------------
__global__ void __launch_bounds__(256) k_qkv()
{
    __shared__ float sAh[2 * AH_SZ], sAl[2 * AH_SZ], sBh[2 * BH_SZ], sBl[2 * BH_SZ];
    __shared__ int arow[128];
    int bx = blockIdx.x;  // 0..11 (col tile of 1536)
    int by = blockIdx.y;  // 0..47
    int tid = threadIdx.x;
    if (tid < 128) arow[tid] = by * 128 + tid;
    __syncthreads();

    float acc[4][4][4] = {};
    gemm_pre(g_h_hi, g_h_lo, DMODEL, arow,
             s_qkvw_hi + bx * 128, s_qkvw_lo + bx * 128, 1536, DMODEL,
             acc, sAh, sAl, sBh, sBl);

    int warp = tid >> 5, lane = tid & 31, gid = lane >> 2, tig = lane & 3;
    int wm = (warp & 1) * 64, wn = (warp >> 1) * 32;
    #pragma unroll
    for (int i = 0; i < 4; i++) {
        #pragma unroll
        for (int j = 0; j < 4; j++) {
            #pragma unroll
            for (int rg = 0; rg < 4; rg++) {
                int r = wm + i * 16 + gid + (rg >> 1) * 8;
                int c = wn + j * 8 + tig * 2 + (rg & 1);
                int gr = by * 128 + r;
                int gc = bx * 128 + c;
                int bb = gr / NTOT, n = gr % NTOT;
                int which = gc >> 9;
                int cc = gc & 511;
                int h = cc >> 6, hd = cc & 63;
                float* dst = (which == 0) ? g_q : (which == 1) ? g_k : g_v;
                dst[(((size_t)bb * NHEADS + h) * NTOT + n) * HDIM + hd] = acc[i][j][rg];
            }
        }
    }
}

// ---------------- K3: attention (flash-style, 1 query row / thread) ---------
__global__ void __launch_bounds__(128) k_attn()
{
    int bh = blockIdx.x;                       // 64
    int n  = blockIdx.y * 128 + threadIdx.x;   // query row
    const float* qp = g_q + ((size_t)bh * NTOT + n) * HDIM;
    float q[HDIM];
    #pragma unroll
    for (int i = 0; i < HDIM; i += 4) {
        float4 t4 = *(const float4*)(qp + i);
        q[i] = t4.x * 0.125f; q[i+1] = t4.y * 0.125f;
        q[i+2] = t4.z * 0.125f; q[i+3] = t4.w * 0.125f;
    }
    float acc[HDIM];
    #pragma unroll
    for (int i = 0; i < HDIM; i++) acc[i] = 0.f;
    float m = -1e30f, l = 0.f;

    __shared__ float Ks[32 * 64], Vs[32 * 64];
    const float* kb = g_k + (size_t)bh * NTOT * HDIM;
    const float* vb = g_v + (size_t)bh * NTOT * HDIM;

    for (int c = 0; c < NTOT; c += 32) {
        __syncthreads();
        #pragma unroll
        for (int i = threadIdx.x; i < 512; i += 128) {
            *(float4*)(Ks + i * 4) = *(const float4*)(kb + c * 64 + i * 4);
            *(float4*)(Vs + i * 4) = *(const float4*)(vb + c * 64 + i * 4);
        }
        __syncthreads();

        float s[32];
        #pragma unroll
        for (int j = 0; j < 32; j++) {
            float d0 = 0.f;
            #pragma unroll
            for (int d = 0; d < 64; d += 4) {
                float4 kk = *(const float4*)(Ks + j * 64 + d);
                d0 += q[d] * kk.x + q[d+1] * kk.y + q[d+2] * kk.z + q[d+3] * kk.w;
            }
            s[j] = d0;
        }
        float cm = s[0];
        #pragma unroll
        for (int j = 1; j < 32; j++) cm = fmaxf(cm, s[j]);
        float mn = fmaxf(m, cm);
        float f = __expf(m - mn);
        m = mn;
        l *= f;
        #pragma unroll
        for (int d = 0; d < 64; d++) acc[d] *= f;
        #pragma unroll
        for (int j = 0; j < 32; j++) {
            float p = __expf(s[j] - m);
            l += p;
            #pragma unroll
            for (int d = 0; d < 64; d += 4) {
                float4 vv = *(const float4*)(Vs + j * 64 + d);
                acc[d]   += p * vv.x; acc[d+1] += p * vv.y;
                acc[d+2] += p * vv.z; acc[d+3] += p * vv.w;
            }
        }
    }
    float inv = 1.f / l;
    int bb = bh >> 3, h = bh & 7;
    float* op = g_o + ((size_t)bb * NTOT + n) * DMODEL + h * HDIM;
    #pragma unroll
    for (int d = 0; d < 64; d++) op[d] = acc[d] * inv;
}

// ---------------- K4: proj GEMM, x2 = 2*(o @ proj_w + proj_b) ---------------
__global__ void __launch_bounds__(256) k_proj(const float* __restrict__ pb)
{
    __shared__ float sAh[2 * AH_SZ], sAl[2 * AH_SZ], sBh[2 * BH_SZ], sBl[2 * BH_SZ];
    __shared__ int arow[128];
    int bx = blockIdx.x, by = blockIdx.y;
    int tid = threadIdx.x;
    if (tid < 128) arow[tid] = by * 128 + tid;
    __syncthreads();

    float acc[4][4][4] = {};
    gemm_pre(g_o_hi, g_o_lo, DMODEL, arow,
             s_pw_hi + bx * 128, s_pw_lo + bx * 128, DMODEL, DMODEL,
             acc, sAh, sAl, sBh, sBl);

    int warp = tid >> 5, lane = tid & 31, gid = lane >> 2, tig = lane & 3;
    int wm = (warp & 1) * 64, wn = (warp >> 1) * 32;
    #pragma unroll
    for (int i = 0; i < 4; i++) {
        #pragma unroll
        for (int j = 0; j < 4; j++) {
            #pragma unroll
            for (int rg = 0; rg < 4; rg++) {
                int r = wm + i * 16 + gid + (rg >> 1) * 8;
                int c = wn + j * 8 + tig * 2 + (rg & 1);
                int gr = by * 128 + r;
                int gc = bx * 128 + c;
                g_x2[(size_t)gr * DMODEL + gc] = 2.f * (acc[i][j][rg] + pb[gc]);
            }
        }
    }
}

// ---------------- K5: LN2 + gate softmax + top2 routing ---------------------
__global__ void __launch_bounds__(128) k_gate(
    const float* __restrict__ n2w, const float* __restrict__ n2b,
    const float* __restrict__ gw)
{
    int t = blockIdx.x, tid = threadIdx.x;
    __shared__ float hs[DMODEL];
    __shared__ float red[64];
    const float* xr = g_x2 + (size_t)t * DMODEL;
    float v[4]; float s = 0.f, ss = 0.f;
    #pragma unroll
    for (int i = 0; i < 4; i++) {
        v[i] = xr[tid + i * 128];
        s += v[i]; ss += v[i] * v[i];
    }
    blockReduce2(s, ss, red);
    __shared__ float mu, rstd;
    if (tid == 0) {
        float m = s * (1.f / 512.f);
        mu = m; rstd = rsqrtf(ss * (1.f / 512.f) - m * m + 1e-5f);
    }
    __syncthreads();
    #pragma unroll
    for (int i = 0; i < 4; i++) {
        int d = tid + i * 128;
        float hv = (v[i] - mu) * rstd * n2w[d] + n2b[d];
        hs[d] = hv;
        store_split(g_hn_hi, g_hn_lo, (size_t)t * DMODEL + d, hv);
    }
    __syncthreads();
    int e = tid >> 4, ln = tid & 15;
    float p = 0.f;
    for (int d = ln; d < DMODEL; d += 16) p += hs[d] * gw[d * NEXP + e];
    #pragma unroll
    for (int o = 8; o; o >>= 1) p += __shfl_down_sync(0xffffffffu, p, o, 16);
    __shared__ float lg[NEXP];
    if (ln == 0) lg[e] = p;
    __syncthreads();
    if (tid == 0) {
        int i0 = 0; float b0 = lg[0];
        #pragma unroll
        for (int i = 1; i < NEXP; i++) if (lg[i] > b0) { b0 = lg[i]; i0 = i; }
        int i1 = -1; float b1 = -1e30f;
        #pragma unroll
        for (int i = 0; i < NEXP; i++) {
            if (i == i0) continue;
            if (lg[i] > b1) { b1 = lg[i]; i1 = i; }
        }
        float c0 = 1.f / (1.f + __expf(b1 - b0));
        int p0 = atomicAdd(&g_cnt[i0], 1);
        g_rows[i0 * SLOTS + p0] = t * 2;
        int p1 = atomicAdd(&g_cnt[i1], 1);
        g_rows[i1 * SLOTS + p1] = t * 2 + 1;
        g_conf[t * 2] = c0;
        g_conf[t * 2 + 1] = 1.f - c0;
    }
}

// ---------------- K6: grouped MoE GEMM 1 (hn @ w1, gelu) --------------------
__global__ void __launch_bounds__(256) k_moe1(const float* __restrict__ b1)
{
    int e = blockIdx.z, by = blockIdx.y, bx = blockIdx.x;
    int cnt = g_cnt[e];
    if (by * 128 >= cnt) return;
    __shared__ float sAh[2 * AH_SZ], sAl[2 * AH_SZ], sBh[2 * BH_SZ], sBl[2 * BH_SZ];
    __shared__ int arow[128], ent_s[128];
    int tid = threadIdx.x;
    if (tid < 128) {
        int rr = by * 128 + tid;
        int ent = (rr < cnt) ? g_rows[e * SLOTS + rr] : -1;
        ent_s[tid] = ent;
        arow[tid] = (ent >= 0) ? (ent >> 1) : -1;
    }
    __syncthreads();

    float acc[4][4][4] = {};
    gemm_pre(g_hn_hi, g_hn_lo, DMODEL, arow,
             s_w1_hi + (size_t)e * 512 * 1024 + bx * 128,
             s_w1_lo + (size_t)e * 512 * 1024 + bx * 128, DFF, DMODEL,
             acc, sAh, sAl, sBh, sBl);

    int warp = tid >> 5, lane = tid & 31, gid = lane >> 2, tig = lane & 3;
    int wm = (warp & 1) * 64, wn = (warp >> 1) * 32;
    #pragma unroll
    for (int i = 0; i < 4; i++) {
        #pragma unroll
        for (int j = 0; j < 4; j++) {
            #pragma unroll
            for (int rg = 0; rg < 4; rg++) {
                int r = wm + i * 16 + gid + (rg >> 1) * 8;
                int ent = ent_s[r];
                if (ent < 0) continue;
                int gc = bx * 128 + wn + j * 8 + tig * 2 + (rg & 1);
                float vv = acc[i][j][rg] + b1[e * DFF + gc];
                vv = 0.5f * vv * (1.f + erff(vv * 0.70710678118654752f));
                store_split(g_hid_hi, g_hid_lo, (size_t)ent * DFF + gc, vv);
            }
        }
    }
}

// ---------------- K7: grouped MoE GEMM 2 (hid @ w2, *conf) ------------------
__global__ void __launch_bounds__(256) k_moe2(const float* __restrict__ b2)
{
    int e = blockIdx.z, by = blockIdx.y, bx = blockIdx.x;
    int cnt = g_cnt[e];
    if (by * 128 >= cnt) return;
    __shared__ float sAh[2 * AH_SZ], sAl[2 * AH_SZ], sBh[2 * BH_SZ], sBl[2 * BH_SZ];
    __shared__ int arow[128], ent_s[128];
    int tid = threadIdx.x;
    if (tid < 128) {
        int rr = by * 128 + tid;
        int ent = (rr < cnt) ? g_rows[e * SLOTS + rr] : -1;
        ent_s[tid] = ent;
        arow[tid] = ent;
    }
    __syncthreads();

    float acc[4][4][4] = {};
    gemm_pre(g_hid_hi, g_hid_lo, DFF, arow,
             s_w2_hi + (size_t)e * 1024 * 512 + bx * 128,
             s_w2_lo + (size_t)e * 1024 * 512 + bx * 128, DMODEL, DFF,
             acc, sAh, sAl, sBh, sBl);

    int warp = tid >> 5, lane = tid & 31, gid = lane >> 2, tig = lane & 3;
    int wm = (warp & 1) * 64, wn = (warp >> 1) * 32;
    #pragma unroll
    for (int i = 0; i < 4; i++) {
        #pragma unroll
        for (int j = 0; j < 4; j++) {
            #pragma unroll
            for (int rg = 0; rg < 4; rg++) {
                int r = wm + i * 16 + gid + (rg >> 1) * 8;
                int ent = ent_s[r];
                if (ent < 0) continue;
                float cf = g_conf[ent];
                int gc = bx * 128 + wn + j * 8 + tig * 2 + (rg & 1);
                g_comb[(size_t)ent * DMODEL + gc] = cf * (acc[i][j][rg] + b2[e * DMODEL + gc]);
            }
        }
    }
}

// ---------------- K8: residual + LN(ln1) → out ------------------------------
__global__ void __launch_bounds__(256) k_final(
    const float* __restrict__ lw, const float* __restrict__ lb,
    float* __restrict__ out)
{
    int t = blockIdx.x, tid = threadIdx.x;
    const float* xr = g_x2 + (size_t)t * DMODEL;
    const float* c0 = g_comb + (size_t)(t * 2) * DMODEL;
    const float* c1 = g_comb + (size_t)(t * 2 + 1) * DMODEL;
    float v0 = xr[tid]       + c0[tid]       + c1[tid];
    float v1 = xr[tid + 256] + c0[tid + 256] + c1[tid + 256];
    float s = v0 + v1, ss = v0 * v0 + v1 * v1;
    __shared__ float red[64];
    blockReduce2(s, ss, red);
    __shared__ float mu, rstd;
    if (tid == 0) {
        float m = s * (1.f / 512.f);
        mu = m; rstd = rsqrtf(ss * (1.f / 512.f) - m * m + 1e-5f);
    }
    __syncthreads();
    out[(size_t)t * DMODEL + tid]       = (v0 - mu) * rstd * lw[tid]       + lb[tid];
    out[(size_t)t * DMODEL + tid + 256] = (v1 - mu) * rstd * lw[tid + 256] + lb[tid + 256];
}

// ---------------- launch -----------------------------------------------------
extern "C" void kernel_launch(void* const* d_in, const int* in_sizes, int n_in,
                              void* d_out, int out_size)
{
    const float* x1   = (const float*)d_in[0];
    const float* x2   = (const float*)d_in[1];
    const float* x3   = (const float*)d_in[2];
    const float* n1w  = (const float*)d_in[3];
    const float* n1b  = (const float*)d_in[4];
    const float* n2w  = (const float*)d_in[5];
    const float* n2b  = (const float*)d_in[6];
    const float* l1w  = (const float*)d_in[7];
    const float* l1b  = (const float*)d_in[8];
    const float* qw   = (const float*)d_in[9];
    const float* kvw  = (const float*)d_in[10];
    const float* pw   = (const float*)d_in[11];
    const float* pb   = (const float*)d_in[12];
    const float* gw   = (const float*)d_in[13];
    const float* ew1  = (const float*)d_in[14];
    const float* eb1  = (const float*)d_in[15];
    const float* ew2  = (const float*)d_in[16];
    const float* ew2b = (const float*)d_in[17];
    float* out = (float*)d_out;

    k_split_w<<<(NSPLIT4 + 255) / 256, 256>>>(qw, kvw, pw, ew1, ew2);
    k_ln1<<<TOK, 256>>>(x1, x2, x3, n1w, n1b);
    { dim3 g(12, 48); k_qkv<<<g, 256>>>(); }
    { dim3 g(64, 6);  k_attn<<<g, 128>>>(); }
    k_split_o<<<TOK * DMODEL / 4 / 256, 256>>>();
    { dim3 g(4, 48);  k_proj<<<g, 256>>>(pb); }
    k_gate<<<TOK, 128>>>(n2w, n2b, gw);
    { dim3 g(8, 96, 8); k_moe1<<<g, 256>>>(eb1); }
    { dim3 g(4, 96, 8); k_moe2<<<g, 256>>>(ew2b); }
    k_final<<<TOK, 256>>>(l1w, l1b, out);
}

// round 10
// speedup vs baseline: 1.0447x; 1.0303x over previous
#include <cuda_runtime.h>
#include <math.h>
#include <stdint.h>

// Problem constants
#define DMODEL 512
#define NHEADS 8
#define HDIM   64
#define NEXP   8
#define DFF    1024
#define BATCH  8
#define NCHUNK 256
#define NTOT   768            // 3 * 256
#define TOK    (BATCH * NTOT) // 6144
#define SLOTS  (TOK * 2)      // 12288 routed (token, slot) rows

// ---------------- scratch ----------------------------------------------------
__device__ float g_h  [TOK * DMODEL];    // LN1 output
__device__ float g_q  [TOK * DMODEL];    // [bh][n][hd]
__device__ float g_k  [TOK * DMODEL];
__device__ float g_v  [TOK * DMODEL];
__device__ float g_o  [TOK * DMODEL];    // attn out, [token][h*64+hd]
__device__ float g_x2 [TOK * DMODEL];    // 2*(o@proj + b)
__device__ float g_hn [TOK * DMODEL];    // LN2 output
__device__ float g_hid[SLOTS * DFF];     // gelu(hn @ w1 + b1), by slot entry
__device__ float g_comb[SLOTS * DMODEL]; // conf * (hid @ w2 + b2), by slot entry
__device__ int   g_rows[NEXP * SLOTS];   // per-expert slot-entry lists
__device__ int   g_cnt [NEXP];
__device__ float g_conf[SLOTS];

// ---------------- helpers ----------------------------------------------------
__device__ __forceinline__ void blockReduce2(float& a, float& b, float* sm) {
    #pragma unroll
    for (int o = 16; o; o >>= 1) {
        a += __shfl_down_sync(0xffffffffu, a, o);
        b += __shfl_down_sync(0xffffffffu, b, o);
    }
    int w = threadIdx.x >> 5, l = threadIdx.x & 31;
    int nw = blockDim.x >> 5;
    if (l == 0) { sm[w] = a; sm[w + 32] = b; }
    __syncthreads();
    if (w == 0) {
        a = (l < nw) ? sm[l] : 0.f;
        b = (l < nw) ? sm[l + 32] : 0.f;
        #pragma unroll
        for (int o = 16; o; o >>= 1) {
            a += __shfl_down_sync(0xffffffffu, a, o);
            b += __shfl_down_sync(0xffffffffu, b, o);
        }
    }
}

__device__ __forceinline__ uint32_t f2tf32(float f) {
    uint32_t r;
    asm("cvt.rna.tf32.f32 %0, %1;" : "=r"(r) : "f"(f));
    return r;
}

// split x into hi (tf32) + lo (tf32 of residual); hi+lo ~ 21-bit accurate
__device__ __forceinline__ void split_tf32(float x, uint32_t& hi, uint32_t& lo) {
    uint32_t h = f2tf32(x);
    float r = x - __uint_as_float(h);
    hi = h;
    lo = f2tf32(r);
}

__device__ __forceinline__ void mma_tf32(float* c, const uint32_t* a,
                                         const uint32_t* b) {
    asm volatile(
        "mma.sync.aligned.m16n8k8.row.col.f32.tf32.tf32.f32 "
        "{%0,%1,%2,%3}, {%4,%5,%6,%7}, {%8,%9}, {%0,%1,%2,%3};"
        : "+f"(c[0]), "+f"(c[1]), "+f"(c[2]), "+f"(c[3])
        : "r"(a[0]), "r"(a[1]), "r"(a[2]), "r"(a[3]), "r"(b[0]), "r"(b[1]));
}

// 16B async copy, zero-fill when !valid
__device__ __forceinline__ void cp_async16(float* dst, const float* src, bool valid) {
    uint32_t d = (uint32_t)__cvta_generic_to_shared(dst);
    int sz = valid ? 16 : 0;
    asm volatile("cp.async.cg.shared.global [%0], [%1], 16, %2;\n"
                 :: "r"(d), "l"(src), "r"(sz));
}
__device__ __forceinline__ void cp_commit() {
    asm volatile("cp.async.commit_group;\n");
}
template <int N>
__device__ __forceinline__ void cp_wait() {
    asm volatile("cp.async.wait_group %0;\n" :: "n"(N));
}

// ---------------- K1: LN1 on concat(x1,x2,x3); also zero routing counters ----
__global__ void __launch_bounds__(256) k_ln1(
    const float* __restrict__ x1, const float* __restrict__ x2,
    const float* __restrict__ x3,
    const float* __restrict__ w, const float* __restrict__ b)
{
    int t = blockIdx.x, tid = threadIdx.x;
    if (t == 0 && tid < NEXP) g_cnt[tid] = 0;
    int bb = t / NTOT, pos = t % NTOT;
    const float* src = (pos < NCHUNK) ? x1 : (pos < 2 * NCHUNK) ? x2 : x3;
    const float* row = src + ((size_t)bb * NCHUNK + (pos % NCHUNK)) * DMODEL;
    float v0 = row[tid], v1 = row[tid + 256];
    float s = v0 + v1, ss = v0 * v0 + v1 * v1;
    __shared__ float red[64];
    blockReduce2(s, ss, red);
    __shared__ float mu, rstd;
    if (tid == 0) {
        float m = s * (1.f / 512.f);
        float var = ss * (1.f / 512.f) - m * m;
        mu = m; rstd = rsqrtf(var + 1e-5f);
    }
    __syncthreads();
    float* dst = g_h + (size_t)t * DMODEL;
    dst[tid]       = (v0 - mu) * rstd * w[tid]       + b[tid];
    dst[tid + 256] = (v1 - mu) * rstd * w[tid + 256] + b[tid + 256];
}

// ---------------- 3xTF32 pipelined 128x128x16 GEMM mainloop -----------------
// 256 threads = 8 warps, warp grid 2(M) x 4(N), warp tile 64x32.
// fp32 tiles double-buffered via cp.async; hi/lo split in consumer registers.
// acc += Ah*Bh + Ah*Bl + Al*Bh (fp32-comparable precision).
#define AP 20            // A smem row stride (16 k + 4 pad) — 80B, 16B-aligned
#define BP 136           // B smem row stride (128 n + 8 pad) — 544B, 16B-aligned
#define A_SZ (128 * AP)
#define B_SZ (16 * BP)

__device__ __forceinline__ void gemm_3xtf32(
    const float* __restrict__ A, int lda, const int* __restrict__ arow_s,
    const float* __restrict__ B, int ldb, int Kdim,
    float (&acc)[4][4][4], float* As, float* Bs)
{
    const int tid  = threadIdx.x;
    const int warp = tid >> 5, lane = tid & 31;
    const int gid  = lane >> 2, tig = lane & 3;
    const int wm   = (warp & 1) * 64;
    const int wn   = (warp >> 1) * 32;

    // producer thread's fixed coordinates
    const int ar0 = tid >> 2,  ac0 = (tid & 3) * 4;          // A elems 0,1
    const int ar1 = (tid + 256) >> 2, ac1 = ac0;             // (e&3) same
    const int br0 = tid >> 5,  bc0 = (tid & 31) * 4;
    const int br1 = (tid + 256) >> 5, bc1 = bc0;
    const int ga0 = arow_s[ar0], ga1 = arow_s[ar1];

    auto load_tile = [&](int k0, int buf) {
        float* Ad = As + buf * A_SZ;
        float* Bd = Bs + buf * B_SZ;
        cp_async16(Ad + ar0 * AP + ac0,
                   A + (size_t)(ga0 < 0 ? 0 : ga0) * lda + k0 + ac0, ga0 >= 0);
        cp_async16(Ad + ar1 * AP + ac1,
                   A + (size_t)(ga1 < 0 ? 0 : ga1) * lda + k0 + ac1, ga1 >= 0);
        cp_async16(Bd + br0 * BP + bc0, B + (size_t)(k0 + br0) * ldb + bc0, true);
        cp_async16(Bd + br1 * BP + bc1, B + (size_t)(k0 + br1) * ldb + bc1, true);
    };

    const int nk = Kdim >> 4;
    load_tile(0, 0);
    cp_commit();

    for (int it = 0; it < nk; it++) {
        if (it + 1 < nk) load_tile((it + 1) << 4, (it + 1) & 1);
        cp_commit();
        cp_wait<1>();
        __syncthreads();

        const float* Af = As + (it & 1) * A_SZ;
        const float* Bf = Bs + (it & 1) * B_SZ;
        #pragma unroll
        for (int kk = 0; kk < 2; kk++) {
            uint32_t afh[4][4], afl[4][4], bfh[4][2], bfl[4][2];
            #pragma unroll
            for (int i = 0; i < 4; i++) {
                int off = (wm + i * 16 + gid) * AP + kk * 8 + tig;
                split_tf32(Af[off],              afh[i][0], afl[i][0]);
                split_tf32(Af[off + 8 * AP],     afh[i][1], afl[i][1]);
                split_tf32(Af[off + 4],          afh[i][2], afl[i][2]);
                split_tf32(Af[off + 8 * AP + 4], afh[i][3], afl[i][3]);
            }
            #pragma unroll
            for (int j = 0; j < 4; j++) {
                int off = (kk * 8 + tig) * BP + wn + j * 8 + gid;
                split_tf32(Bf[off],          bfh[j][0], bfl[j][0]);
                split_tf32(Bf[off + 4 * BP], bfh[j][1], bfl[j][1]);
            }
            #pragma unroll
            for (int i = 0; i < 4; i++)
                #pragma unroll
                for (int j = 0; j < 4; j++) {
                    mma_tf32(acc[i][j], afl[i], bfh[j]);  // lo*hi
                    mma_tf32(acc[i][j], afh[i], bfl[j]);  // hi*lo
                    mma_tf32(acc[i][j], afh[i], bfh[j]);  // hi*hi
                }
        }
        __syncthreads();
    }
}

// Epilogue fragment coords: rows r0=wm+i*16+gid, r1=r0+8;
// cols c0=wn+j*8+tig*2, c0+1. regs: [0]=(r0,c0) [1]=(r0,c0+1) [2]=(r1,c0) [3]=(r1,c0+1)

// ---------------- K2: QKV GEMM (h @ [q_w | kv_w]) ---------------------------
__global__ void __launch_bounds__(256) k_qkv(
    const float* __restrict__ qw, const float* __restrict__ kvw)
{
    __shared__ float As[2 * A_SZ], Bs[2 * B_SZ];
    __shared__ int arow[128];
    int bx = blockIdx.x;  // 0..11 (col tile of 1536)
    int by = blockIdx.y;  // 0..47
    int tid = threadIdx.x;
    if (tid < 128) arow[tid] = by * 128 + tid;
    __syncthreads();

    const float* B; int ldb;
    if (bx < 4) { B = qw + bx * 128;            ldb = 512;  }
    else        { B = kvw + (bx * 128 - 512);   ldb = 1024; }

    float acc[4][4][4] = {};
    gemm_3xtf32(g_h, DMODEL, arow, B, ldb, DMODEL, acc, As, Bs);

    int warp = tid >> 5, lane = tid & 31, gid = lane >> 2, tig = lane & 3;
    int wm = (warp & 1) * 64, wn = (warp >> 1) * 32;
    #pragma unroll
    for (int i = 0; i < 4; i++) {
        #pragma unroll
        for (int j = 0; j < 4; j++) {
            #pragma unroll
            for (int rg = 0; rg < 4; rg++) {
                int r = wm + i * 16 + gid + (rg >> 1) * 8;
                int c = wn + j * 8 + tig * 2 + (rg & 1);
                int gr = by * 128 + r;
                int gc = bx * 128 + c;
                int bb = gr / NTOT, n = gr % NTOT;
                int which = gc >> 9;
                int cc = gc & 511;
                int h = cc >> 6, hd = cc & 63;
                float* dst = (which == 0) ? g_q : (which == 1) ? g_k : g_v;
                dst[(((size_t)bb * NHEADS + h) * NTOT + n) * HDIM + hd] = acc[i][j][rg];
            }
        }
    }
}

// ---------------- K3: attention (flash-style, 2 threads / query row) --------
// Lane pair (2k, 2k+1): thread owns 32 of 64 head dims. Full dot via shfl_xor.
// Both pair threads compute identical s/m/l (pair-sum is fp-commutative).
__global__ void __launch_bounds__(128, 3) k_attn()
{
    int bh = blockIdx.x;                        // 64
    int pr = threadIdx.x >> 1;                  // pair 0..63
    int hf = threadIdx.x & 1;                   // which 32-dim half
    int n  = blockIdx.y * 64 + pr;              // query row
    const float* qp = g_q + ((size_t)bh * NTOT + n) * HDIM + hf * 32;
    float q[32];
    #pragma unroll
    for (int i = 0; i < 32; i += 4) {
        float4 t4 = *(const float4*)(qp + i);
        q[i] = t4.x * 0.125f; q[i+1] = t4.y * 0.125f;
        q[i+2] = t4.z * 0.125f; q[i+3] = t4.w * 0.125f;
    }
    float acc[32];
    #pragma unroll
    for (int i = 0; i < 32; i++) acc[i] = 0.f;
    float m = -1e30f, l = 0.f;

    __shared__ float Ks[32 * 64], Vs[32 * 64];
    const float* kb = g_k + (size_t)bh * NTOT * HDIM;
    const float* vb = g_v + (size_t)bh * NTOT * HDIM;

    for (int c = 0; c < NTOT; c += 32) {
        __syncthreads();
        #pragma unroll
        for (int i = threadIdx.x; i < 512; i += 128) {
            *(float4*)(Ks + i * 4) = *(const float4*)(kb + c * 64 + i * 4);
            *(float4*)(Vs + i * 4) = *(const float4*)(vb + c * 64 + i * 4);
        }
        __syncthreads();

        float s[32];
        #pragma unroll
        for (int j = 0; j < 32; j++) {
            const float* kr = Ks + j * 64 + hf * 32;
            float d0 = 0.f, d1 = 0.f, d2 = 0.f, d3 = 0.f;
            float4 k0 = *(const float4*)(kr);
            float4 k1 = *(const float4*)(kr + 4);
            float4 k2 = *(const float4*)(kr + 8);
            float4 k3 = *(const float4*)(kr + 12);
            float4 k4 = *(const float4*)(kr + 16);
            float4 k5 = *(const float4*)(kr + 20);
            float4 k6 = *(const float4*)(kr + 24);
            float4 k7 = *(const float4*)(kr + 28);
            d0 += q[0]*k0.x + q[1]*k0.y + q[2]*k0.z + q[3]*k0.w;
            d1 += q[4]*k1.x + q[5]*k1.y + q[6]*k1.z + q[7]*k1.w;
            d2 += q[8]*k2.x + q[9]*k2.y + q[10]*k2.z + q[11]*k2.w;
            d3 += q[12]*k3.x + q[13]*k3.y + q[14]*k3.z + q[15]*k3.w;
            d0 += q[16]*k4.x + q[17]*k4.y + q[18]*k4.z + q[19]*k4.w;
            d1 += q[20]*k5.x + q[21]*k5.y + q[22]*k5.z + q[23]*k5.w;
            d2 += q[24]*k6.x + q[25]*k6.y + q[26]*k6.z + q[27]*k6.w;
            d3 += q[28]*k7.x + q[29]*k7.y + q[30]*k7.z + q[31]*k7.w;
            float part = (d0 + d1) + (d2 + d3);
            s[j] = part + __shfl_xor_sync(0xffffffffu, part, 1);
        }
        float cm = s[0];
        #pragma unroll
        for (int j = 1; j < 32; j++) cm = fmaxf(cm, s[j]);
        float mn = fmaxf(m, cm);
        float f = __expf(m - mn);
        m = mn;
        l *= f;
        #pragma unroll
        for (int d = 0; d < 32; d++) acc[d] *= f;
        #pragma unroll
        for (int j = 0; j < 32; j++) {
            float p = __expf(s[j] - m);
            l += p;
            const float* vr = Vs + j * 64 + hf * 32;
            #pragma unroll
            for (int d = 0; d < 32; d += 4) {
                float4 vv = *(const float4*)(vr + d);
                acc[d]   += p * vv.x; acc[d+1] += p * vv.y;
                acc[d+2] += p * vv.z; acc[d+3] += p * vv.w;
            }
        }
    }
    float inv = 1.f / l;
    int bb = bh >> 3, h = bh & 7;
    float* op = g_o + ((size_t)bb * NTOT + n) * DMODEL + h * HDIM + hf * 32;
    #pragma unroll
    for (int d = 0; d < 32; d++) op[d] = acc[d] * inv;
}

// ---------------- K4: proj GEMM, x2 = 2*(o @ proj_w + proj_b) ---------------
__global__ void __launch_bounds__(256) k_proj(
    const float* __restrict__ pw, const float* __restrict__ pb)
{
    __shared__ float As[2 * A_SZ], Bs[2 * B_SZ];
    __shared__ int arow[128];
    int bx = blockIdx.x, by = blockIdx.y;
    int tid = threadIdx.x;
    if (tid < 128) arow[tid] = by * 128 + tid;
    __syncthreads();

    float acc[4][4][4] = {};
    gemm_3xtf32(g_o, DMODEL, arow, pw + bx * 128, DMODEL, DMODEL, acc, As, Bs);

    int warp = tid >> 5, lane = tid & 31, gid = lane >> 2, tig = lane & 3;
    int wm = (warp & 1) * 64, wn = (warp >> 1) * 32;
    #pragma unroll
    for (int i = 0; i < 4; i++) {
        #pragma unroll
        for (int j = 0; j < 4; j++) {
            #pragma unroll
            for (int rg = 0; rg < 4; rg++) {
                int r = wm + i * 16 + gid + (rg >> 1) * 8;
                int c = wn + j * 8 + tig * 2 + (rg & 1);
                int gr = by * 128 + r;
                int gc = bx * 128 + c;
                g_x2[(size_t)gr * DMODEL + gc] = 2.f * (acc[i][j][rg] + pb[gc]);
            }
        }
    }
}

// ---------------- K5: LN2 + gate softmax + top2 routing ---------------------
__global__ void __launch_bounds__(128) k_gate(
    const float* __restrict__ n2w, const float* __restrict__ n2b,
    const float* __restrict__ gw)
{
    int t = blockIdx.x, tid = threadIdx.x;
    __shared__ float hs[DMODEL];
    __shared__ float red[64];
    const float* xr = g_x2 + (size_t)t * DMODEL;
    float v[4]; float s = 0.f, ss = 0.f;
    #pragma unroll
    for (int i = 0; i < 4; i++) {
        v[i] = xr[tid + i * 128];
        s += v[i]; ss += v[i] * v[i];
    }
    blockReduce2(s, ss, red);
    __shared__ float mu, rstd;
    if (tid == 0) {
        float m = s * (1.f / 512.f);
        mu = m; rstd = rsqrtf(ss * (1.f / 512.f) - m * m + 1e-5f);
    }
    __syncthreads();
    #pragma unroll
    for (int i = 0; i < 4; i++) {
        int d = tid + i * 128;
        float hv = (v[i] - mu) * rstd * n2w[d] + n2b[d];
        hs[d] = hv;
        g_hn[(size_t)t * DMODEL + d] = hv;
    }
    __syncthreads();
    int e = tid >> 4, ln = tid & 15;
    float p = 0.f;
    for (int d = ln; d < DMODEL; d += 16) p += hs[d] * gw[d * NEXP + e];
    #pragma unroll
    for (int o = 8; o; o >>= 1) p += __shfl_down_sync(0xffffffffu, p, o, 16);
    __shared__ float lg[NEXP];
    if (ln == 0) lg[e] = p;
    __syncthreads();
    if (tid == 0) {
        int i0 = 0; float b0 = lg[0];
        #pragma unroll
        for (int i = 1; i < NEXP; i++) if (lg[i] > b0) { b0 = lg[i]; i0 = i; }
        int i1 = -1; float b1 = -1e30f;
        #pragma unroll
        for (int i = 0; i < NEXP; i++) {
            if (i == i0) continue;
            if (lg[i] > b1) { b1 = lg[i]; i1 = i; }
        }
        float c0 = 1.f / (1.f + __expf(b1 - b0));
        int p0 = atomicAdd(&g_cnt[i0], 1);
        g_rows[i0 * SLOTS + p0] = t * 2;
        int p1 = atomicAdd(&g_cnt[i1], 1);
        g_rows[i1 * SLOTS + p1] = t * 2 + 1;
        g_conf[t * 2] = c0;
        g_conf[t * 2 + 1] = 1.f - c0;
    }
}

// ---------------- K6: grouped MoE GEMM 1 (hn @ w1, gelu) --------------------
__global__ void __launch_bounds__(256) k_moe1(
    const float* __restrict__ w1, const float* __restrict__ b1)
{
    int e = blockIdx.z, by = blockIdx.y, bx = blockIdx.x;
    int cnt = g_cnt[e];
    if (by * 128 >= cnt) return;
    __shared__ float As[2 * A_SZ], Bs[2 * B_SZ];
    __shared__ int arow[128], ent_s[128];
    int tid = threadIdx.x;
    if (tid < 128) {
        int rr = by * 128 + tid;
        int ent = (rr < cnt) ? g_rows[e * SLOTS + rr] : -1;
        ent_s[tid] = ent;
        arow[tid] = (ent >= 0) ? (ent >> 1) : -1;
    }
    __syncthreads();

    float acc[4][4][4] = {};
    gemm_3xtf32(g_hn, DMODEL, arow,
                w1 + (size_t)e * DMODEL * DFF + bx * 128, DFF, DMODEL, acc, As, Bs);

    int warp = tid >> 5, lane = tid & 31, gid = lane >> 2, tig = lane & 3;
    int wm = (warp & 1) * 64, wn = (warp >> 1) * 32;
    #pragma unroll
    for (int i = 0; i < 4; i++) {
        #pragma unroll
        for (int j = 0; j < 4; j++) {
            #pragma unroll
            for (int rg = 0; rg < 4; rg++) {
                int r = wm + i * 16 + gid + (rg >> 1) * 8;
                int ent = ent_s[r];
                if (ent < 0) continue;
                int gc = bx * 128 + wn + j * 8 + tig * 2 + (rg & 1);
                float vv = acc[i][j][rg] + b1[e * DFF + gc];
                vv = 0.5f * vv * (1.f + erff(vv * 0.70710678118654752f));
                g_hid[(size_t)ent * DFF + gc] = vv;
            }
        }
    }
}

// ---------------- K7: grouped MoE GEMM 2 (hid @ w2, *conf) ------------------
__global__ void __launch_bounds__(256) k_moe2(
    const float* __restrict__ w2, const float* __restrict__ b2)
{
    int e = blockIdx.z, by = blockIdx.y, bx = blockIdx.x;
    int cnt = g_cnt[e];
    if (by * 128 >= cnt) return;
    __shared__ float As[2 * A_SZ], Bs[2 * B_SZ];
    __shared__ int arow[128], ent_s[128];
    int tid = threadIdx.x;
    if (tid < 128) {
        int rr = by * 128 + tid;
        int ent = (rr < cnt) ? g_rows[e * SLOTS + rr] : -1;
        ent_s[tid] = ent;
        arow[tid] = ent;
    }
    __syncthreads();

    float acc[4][4][4] = {};
    gemm_3xtf32(g_hid, DFF, arow,
                w2 + (size_t)e * DFF * DMODEL + bx * 128, DMODEL, DFF, acc, As, Bs);

    int warp = tid >> 5, lane = tid & 31, gid = lane >> 2, tig = lane & 3;
    int wm = (warp & 1) * 64, wn = (warp >> 1) * 32;
    #pragma unroll
    for (int i = 0; i < 4; i++) {
        #pragma unroll
        for (int j = 0; j < 4; j++) {
            #pragma unroll
            for (int rg = 0; rg < 4; rg++) {
                int r = wm + i * 16 + gid + (rg >> 1) * 8;
                int ent = ent_s[r];
                if (ent < 0) continue;
                float cf = g_conf[ent];
                int gc = bx * 128 + wn + j * 8 + tig * 2 + (rg & 1);
                g_comb[(size_t)ent * DMODEL + gc] = cf * (acc[i][j][rg] + b2[e * DMODEL + gc]);
            }
        }
    }
}

// ---------------- K8: residual + LN(ln1) → out ------------------------------
__global__ void __launch_bounds__(256) k_final(
    const float* __restrict__ lw, const float* __restrict__ lb,
    float* __restrict__ out)
{
    int t = blockIdx.x, tid = threadIdx.x;
    const float* xr = g_x2 + (size_t)t * DMODEL;
    const float* c0 = g_comb + (size_t)(t * 2) * DMODEL;
    const float* c1 = g_comb + (size_t)(t * 2 + 1) * DMODEL;
    float v0 = xr[tid]       + c0[tid]       + c1[tid];
    float v1 = xr[tid + 256] + c0[tid + 256] + c1[tid + 256];
    float s = v0 + v1, ss = v0 * v0 + v1 * v1;
    __shared__ float red[64];
    blockReduce2(s, ss, red);
    __shared__ float mu, rstd;
    if (tid == 0) {
        float m = s * (1.f / 512.f);
        mu = m; rstd = rsqrtf(ss * (1.f / 512.f) - m * m + 1e-5f);
    }
    __syncthreads();
    out[(size_t)t * DMODEL + tid]       = (v0 - mu) * rstd * lw[tid]       + lb[tid];
    out[(size_t)t * DMODEL + tid + 256] = (v1 - mu) * rstd * lw[tid + 256] + lb[tid + 256];
}

// ---------------- launch -----------------------------------------------------
extern "C" void kernel_launch(void* const* d_in, const int* in_sizes, int n_in,
                              void* d_out, int out_size)
{
    const float* x1   = (const float*)d_in[0];
    const float* x2   = (const float*)d_in[1];
    const float* x3   = (const float*)d_in[2];
    const float* n1w  = (const float*)d_in[3];
    const float* n1b  = (const float*)d_in[4];
    const float* n2w  = (const float*)d_in[5];
    const float* n2b  = (const float*)d_in[6];
    const float* l1w  = (const float*)d_in[7];
    const float* l1b  = (const float*)d_in[8];
    const float* qw   = (const float*)d_in[9];
    const float* kvw  = (const float*)d_in[10];
    const float* pw   = (const float*)d_in[11];
    const float* pb   = (const float*)d_in[12];
    const float* gw   = (const float*)d_in[13];
    const float* ew1  = (const float*)d_in[14];
    const float* eb1  = (const float*)d_in[15];
    const float* ew2  = (const float*)d_in[16];
    const float* eb2  = (const float*)d_in[17];
    float* out = (float*)d_out;

    k_ln1<<<TOK, 256>>>(x1, x2, x3, n1w, n1b);
    { dim3 g(12, 48); k_qkv<<<g, 256>>>(qw, kvw); }
    { dim3 g(64, 12); k_attn<<<g, 128>>>(); }
    { dim3 g(4, 48);  k_proj<<<g, 256>>>(pw, pb); }
    k_gate<<<TOK, 128>>>(n2w, n2b, gw);
    { dim3 g(8, 96, 8); k_moe1<<<g, 256>>>(ew1, eb1); }
    { dim3 g(4, 96, 8); k_moe2<<<g, 256>>>(ew2, eb2); }
    k_final<<<TOK, 256>>>(l1w, l1b, out);
}

// round 11
// speedup vs baseline: 1.0452x; 1.0004x over previous
#include <cuda_runtime.h>
#include <math.h>
#include <stdint.h>

// Problem constants
#define DMODEL 512
#define NHEADS 8
#define HDIM   64
#define NEXP   8
#define DFF    1024
#define BATCH  8
#define NCHUNK 256
#define NTOT   768            // 3 * 256
#define TOK    (BATCH * NTOT) // 6144
#define SLOTS  (TOK * 2)      // 12288 routed (token, slot) rows

// ---------------- scratch ----------------------------------------------------
__device__ float g_h  [TOK * DMODEL];    // LN1 output
__device__ float g_q  [TOK * DMODEL];    // [bh][n][hd]
__device__ float g_k  [TOK * DMODEL];
__device__ float g_v  [TOK * DMODEL];
__device__ float g_o  [TOK * DMODEL];    // attn out, [token][h*64+hd]
__device__ float g_x2 [TOK * DMODEL];    // 2*(o@proj + b)
__device__ float g_hn [TOK * DMODEL];    // LN2 output
__device__ float g_hid[SLOTS * DFF];     // gelu(hn @ w1 + b1), by slot entry
__device__ float g_comb[SLOTS * DMODEL]; // conf * (hid @ w2 + b2), by slot entry
__device__ int   g_rows[NEXP * SLOTS];   // per-expert slot-entry lists
__device__ int   g_cnt [NEXP];
__device__ float g_conf[SLOTS];

// ---------------- helpers ----------------------------------------------------
__device__ __forceinline__ void blockReduce2(float& a, float& b, float* sm) {
    #pragma unroll
    for (int o = 16; o; o >>= 1) {
        a += __shfl_down_sync(0xffffffffu, a, o);
        b += __shfl_down_sync(0xffffffffu, b, o);
    }
    int w = threadIdx.x >> 5, l = threadIdx.x & 31;
    int nw = blockDim.x >> 5;
    if (l == 0) { sm[w] = a; sm[w + 32] = b; }
    __syncthreads();
    if (w == 0) {
        a = (l < nw) ? sm[l] : 0.f;
        b = (l < nw) ? sm[l + 32] : 0.f;
        #pragma unroll
        for (int o = 16; o; o >>= 1) {
            a += __shfl_down_sync(0xffffffffu, a, o);
            b += __shfl_down_sync(0xffffffffu, b, o);
        }
    }
}

__device__ __forceinline__ uint32_t f2tf32(float f) {
    uint32_t r;
    asm("cvt.rna.tf32.f32 %0, %1;" : "=r"(r) : "f"(f));
    return r;
}

// split x into hi (tf32) + lo (tf32 of residual); hi+lo ~ 21-bit accurate
__device__ __forceinline__ void split_tf32(float x, uint32_t& hi, uint32_t& lo) {
    uint32_t h = f2tf32(x);
    float r = x - __uint_as_float(h);
    hi = h;
    lo = f2tf32(r);
}

__device__ __forceinline__ void mma_tf32(float* c, const uint32_t* a,
                                         const uint32_t* b) {
    asm volatile(
        "mma.sync.aligned.m16n8k8.row.col.f32.tf32.tf32.f32 "
        "{%0,%1,%2,%3}, {%4,%5,%6,%7}, {%8,%9}, {%0,%1,%2,%3};"
        : "+f"(c[0]), "+f"(c[1]), "+f"(c[2]), "+f"(c[3])
        : "r"(a[0]), "r"(a[1]), "r"(a[2]), "r"(a[3]), "r"(b[0]), "r"(b[1]));
}

// 16B async copy, zero-fill when !valid
__device__ __forceinline__ void cp_async16(float* dst, const float* src, bool valid) {
    uint32_t d = (uint32_t)__cvta_generic_to_shared(dst);
    int sz = valid ? 16 : 0;
    asm volatile("cp.async.cg.shared.global [%0], [%1], 16, %2;\n"
                 :: "r"(d), "l"(src), "r"(sz));
}
__device__ __forceinline__ void cp_commit() {
    asm volatile("cp.async.commit_group;\n");
}
template <int N>
__device__ __forceinline__ void cp_wait() {
    asm volatile("cp.async.wait_group %0;\n" :: "n"(N));
}

// ---------------- K1: LN1 on concat(x1,x2,x3); also zero routing counters ----
__global__ void __launch_bounds__(256) k_ln1(
    const float* __restrict__ x1, const float* __restrict__ x2,
    const float* __restrict__ x3,
    const float* __restrict__ w, const float* __restrict__ b)
{
    int t = blockIdx.x, tid = threadIdx.x;
    if (t == 0 && tid < NEXP) g_cnt[tid] = 0;
    int bb = t / NTOT, pos = t % NTOT;
    const float* src = (pos < NCHUNK) ? x1 : (pos < 2 * NCHUNK) ? x2 : x3;
    const float* row = src + ((size_t)bb * NCHUNK + (pos % NCHUNK)) * DMODEL;
    float v0 = row[tid], v1 = row[tid + 256];
    float s = v0 + v1, ss = v0 * v0 + v1 * v1;
    __shared__ float red[64];
    blockReduce2(s, ss, red);
    __shared__ float mu, rstd;
    if (tid == 0) {
        float m = s * (1.f / 512.f);
        float var = ss * (1.f / 512.f) - m * m;
        mu = m; rstd = rsqrtf(var + 1e-5f);
    }
    __syncthreads();
    float* dst = g_h + (size_t)t * DMODEL;
    dst[tid]       = (v0 - mu) * rstd * w[tid]       + b[tid];
    dst[tid + 256] = (v1 - mu) * rstd * w[tid + 256] + b[tid + 256];
}

// ---------------- 3xTF32 pipelined 128x128x16 GEMM mainloop -----------------
// 256 threads = 8 warps, warp grid 2(M) x 4(N), warp tile 64x32.
// fp32 tiles double-buffered via cp.async; hi/lo split in consumer registers.
// acc += Ah*Bh + Ah*Bl + Al*Bh (fp32-comparable precision).
#define AP 20            // A smem row stride (16 k + 4 pad) — 80B, 16B-aligned
#define BP 136           // B smem row stride (128 n + 8 pad) — 544B, 16B-aligned
#define A_SZ (128 * AP)
#define B_SZ (16 * BP)

__device__ __forceinline__ void gemm_3xtf32(
    const float* __restrict__ A, int lda, const int* __restrict__ arow_s,
    const float* __restrict__ B, int ldb, int Kdim,
    float (&acc)[4][4][4], float* As, float* Bs)
{
    const int tid  = threadIdx.x;
    const int warp = tid >> 5, lane = tid & 31;
    const int gid  = lane >> 2, tig = lane & 3;
    const int wm   = (warp & 1) * 64;
    const int wn   = (warp >> 1) * 32;

    // producer thread's fixed coordinates
    const int ar0 = tid >> 2,  ac0 = (tid & 3) * 4;          // A elems 0,1
    const int ar1 = (tid + 256) >> 2, ac1 = ac0;             // (e&3) same
    const int br0 = tid >> 5,  bc0 = (tid & 31) * 4;
    const int br1 = (tid + 256) >> 5, bc1 = bc0;
    const int ga0 = arow_s[ar0], ga1 = arow_s[ar1];

    auto load_tile = [&](int k0, int buf) {
        float* Ad = As + buf * A_SZ;
        float* Bd = Bs + buf * B_SZ;
        cp_async16(Ad + ar0 * AP + ac0,
                   A + (size_t)(ga0 < 0 ? 0 : ga0) * lda + k0 + ac0, ga0 >= 0);
        cp_async16(Ad + ar1 * AP + ac1,
                   A + (size_t)(ga1 < 0 ? 0 : ga1) * lda + k0 + ac1, ga1 >= 0);
        cp_async16(Bd + br0 * BP + bc0, B + (size_t)(k0 + br0) * ldb + bc0, true);
        cp_async16(Bd + br1 * BP + bc1, B + (size_t)(k0 + br1) * ldb + bc1, true);
    };

    const int nk = Kdim >> 4;
    load_tile(0, 0);
    cp_commit();

    for (int it = 0; it < nk; it++) {
        if (it + 1 < nk) load_tile((it + 1) << 4, (it + 1) & 1);
        cp_commit();
        cp_wait<1>();
        __syncthreads();

        const float* Af = As + (it & 1) * A_SZ;
        const float* Bf = Bs + (it & 1) * B_SZ;
        #pragma unroll
        for (int kk = 0; kk < 2; kk++) {
            uint32_t afh[4][4], afl[4][4], bfh[4][2], bfl[4][2];
            #pragma unroll
            for (int i = 0; i < 4; i++) {
                int off = (wm + i * 16 + gid) * AP + kk * 8 + tig;
                split_tf32(Af[off],              afh[i][0], afl[i][0]);
                split_tf32(Af[off + 8 * AP],     afh[i][1], afl[i][1]);
                split_tf32(Af[off + 4],          afh[i][2], afl[i][2]);
                split_tf32(Af[off + 8 * AP + 4], afh[i][3], afl[i][3]);
            }
            #pragma unroll
            for (int j = 0; j < 4; j++) {
                int off = (kk * 8 + tig) * BP + wn + j * 8 + gid;
                split_tf32(Bf[off],          bfh[j][0], bfl[j][0]);
                split_tf32(Bf[off + 4 * BP], bfh[j][1], bfl[j][1]);
            }
            #pragma unroll
            for (int i = 0; i < 4; i++)
                #pragma unroll
                for (int j = 0; j < 4; j++) {
                    mma_tf32(acc[i][j], afl[i], bfh[j]);  // lo*hi
                    mma_tf32(acc[i][j], afh[i], bfl[j]);  // hi*lo
                    mma_tf32(acc[i][j], afh[i], bfh[j]);  // hi*hi
                }
        }
        __syncthreads();
    }
}

// Epilogue fragment coords: rows r0=wm+i*16+gid, r1=r0+8;
// cols c0=wn+j*8+tig*2, c0+1. regs: [0]=(r0,c0) [1]=(r0,c0+1) [2]=(r1,c0) [3]=(r1,c0+1)

// ---------------- K2: QKV GEMM (h @ [q_w | kv_w]) ---------------------------
__global__ void __launch_bounds__(256) k_qkv(
    const float* __restrict__ qw, const float* __restrict__ kvw)
{
    __shared__ float As[2 * A_SZ], Bs[2 * B_SZ];
    __shared__ int arow[128];
    int bx = blockIdx.x;  // 0..11 (col tile of 1536)
    int by = blockIdx.y;  // 0..47
    int tid = threadIdx.x;
    if (tid < 128) arow[tid] = by * 128 + tid;
    __syncthreads();

    const float* B; int ldb;
    if (bx < 4) { B = qw + bx * 128;            ldb = 512;  }
    else        { B = kvw + (bx * 128 - 512);   ldb = 1024; }

    float acc[4][4][4] = {};
    gemm_3xtf32(g_h, DMODEL, arow, B, ldb, DMODEL, acc, As, Bs);

    int warp = tid >> 5, lane = tid & 31, gid = lane >> 2, tig = lane & 3;
    int wm = (warp & 1) * 64, wn = (warp >> 1) * 32;
    #pragma unroll
    for (int i = 0; i < 4; i++) {
        #pragma unroll
        for (int j = 0; j < 4; j++) {
            #pragma unroll
            for (int rg = 0; rg < 4; rg++) {
                int r = wm + i * 16 + gid + (rg >> 1) * 8;
                int c = wn + j * 8 + tig * 2 + (rg & 1);
                int gr = by * 128 + r;
                int gc = bx * 128 + c;
                int bb = gr / NTOT, n = gr % NTOT;
                int which = gc >> 9;
                int cc = gc & 511;
                int h = cc >> 6, hd = cc & 63;
                float* dst = (which == 0) ? g_q : (which == 1) ? g_k : g_v;
                dst[(((size_t)bb * NHEADS + h) * NTOT + n) * HDIM + hd] = acc[i][j][rg];
            }
        }
    }
}

// ---------------- K3: attention (flash-style, 2 threads / query row) --------
// Lane pair (2k, 2k+1): thread owns 32 of 64 head dims. Full dot via shfl_xor.
// Both pair threads compute identical s/m/l (pair-sum is fp-commutative).
__global__ void __launch_bounds__(128, 3) k_attn()
{
    int bh = blockIdx.x;                        // 64
    int pr = threadIdx.x >> 1;                  // pair 0..63
    int hf = threadIdx.x & 1;                   // which 32-dim half
    int n  = blockIdx.y * 64 + pr;              // query row
    const float* qp = g_q + ((size_t)bh * NTOT + n) * HDIM + hf * 32;
    float q[32];
    #pragma unroll
    for (int i = 0; i < 32; i += 4) {
        float4 t4 = *(const float4*)(qp + i);
        q[i] = t4.x * 0.125f; q[i+1] = t4.y * 0.125f;
        q[i+2] = t4.z * 0.125f; q[i+3] = t4.w * 0.125f;
    }
    float acc[32];
    #pragma unroll
    for (int i = 0; i < 32; i++) acc[i] = 0.f;
    float m = -1e30f, l = 0.f;

    __shared__ float Ks[32 * 64], Vs[32 * 64];
    const float* kb = g_k + (size_t)bh * NTOT * HDIM;
    const float* vb = g_v + (size_t)bh * NTOT * HDIM;

    for (int c = 0; c < NTOT; c += 32) {
        __syncthreads();
        #pragma unroll
        for (int i = threadIdx.x; i < 512; i += 128) {
            *(float4*)(Ks + i * 4) = *(const float4*)(kb + c * 64 + i * 4);
            *(float4*)(Vs + i * 4) = *(const float4*)(vb + c * 64 + i * 4);
        }
        __syncthreads();

        float s[32];
        #pragma unroll
        for (int j = 0; j < 32; j++) {
            const float* kr = Ks + j * 64 + hf * 32;
            float d0 = 0.f, d1 = 0.f, d2 = 0.f, d3 = 0.f;
            float4 k0 = *(const float4*)(kr);
            float4 k1 = *(const float4*)(kr + 4);
            float4 k2 = *(const float4*)(kr + 8);
            float4 k3 = *(const float4*)(kr + 12);
            float4 k4 = *(const float4*)(kr + 16);
            float4 k5 = *(const float4*)(kr + 20);
            float4 k6 = *(const float4*)(kr + 24);
            float4 k7 = *(const float4*)(kr + 28);
            d0 += q[0]*k0.x + q[1]*k0.y + q[2]*k0.z + q[3]*k0.w;
            d1 += q[4]*k1.x + q[5]*k1.y + q[6]*k1.z + q[7]*k1.w;
            d2 += q[8]*k2.x + q[9]*k2.y + q[10]*k2.z + q[11]*k2.w;
            d3 += q[12]*k3.x + q[13]*k3.y + q[14]*k3.z + q[15]*k3.w;
            d0 += q[16]*k4.x + q[17]*k4.y + q[18]*k4.z + q[19]*k4.w;
            d1 += q[20]*k5.x + q[21]*k5.y + q[22]*k5.z + q[23]*k5.w;
            d2 += q[24]*k6.x + q[25]*k6.y + q[26]*k6.z + q[27]*k6.w;
            d3 += q[28]*k7.x + q[29]*k7.y + q[30]*k7.z + q[31]*k7.w;
            float part = (d0 + d1) + (d2 + d3);
            s[j] = part + __shfl_xor_sync(0xffffffffu, part, 1);
        }
        float cm = s[0];
        #pragma unroll
        for (int j = 1; j < 32; j++) cm = fmaxf(cm, s[j]);
        float mn = fmaxf(m, cm);
        float f = __expf(m - mn);
        m = mn;
        l *= f;
        #pragma unroll
        for (int d = 0; d < 32; d++) acc[d] *= f;
        #pragma unroll
        for (int j = 0; j < 32; j++) {
            float p = __expf(s[j] - m);
            l += p;
            const float* vr = Vs + j * 64 + hf * 32;
            #pragma unroll
            for (int d = 0; d < 32; d += 4) {
                float4 vv = *(const float4*)(vr + d);
                acc[d]   += p * vv.x; acc[d+1] += p * vv.y;
                acc[d+2] += p * vv.z; acc[d+3] += p * vv.w;
            }
        }
    }
    float inv = 1.f / l;
    int bb = bh >> 3, h = bh & 7;
    float* op = g_o + ((size_t)bb * NTOT + n) * DMODEL + h * HDIM + hf * 32;
    #pragma unroll
    for (int d = 0; d < 32; d++) op[d] = acc[d] * inv;
}

// ---------------- K4: proj GEMM, x2 = 2*(o @ proj_w + proj_b) ---------------
__global__ void __launch_bounds__(256) k_proj(
    const float* __restrict__ pw, const float* __restrict__ pb)
{
    __shared__ float As[2 * A_SZ], Bs[2 * B_SZ];
    __shared__ int arow[128];
    int bx = blockIdx.x, by = blockIdx.y;
    int tid = threadIdx.x;
    if (tid < 128) arow[tid] = by * 128 + tid;
    __syncthreads();

    float acc[4][4][4] = {};
    gemm_3xtf32(g_o, DMODEL, arow, pw + bx * 128, DMODEL, DMODEL, acc, As, Bs);

    int warp = tid >> 5, lane = tid & 31, gid = lane >> 2, tig = lane & 3;
    int wm = (warp & 1) * 64, wn = (warp >> 1) * 32;
    #pragma unroll
    for (int i = 0; i < 4; i++) {
        #pragma unroll
        for (int j = 0; j < 4; j++) {
            #pragma unroll
            for (int rg = 0; rg < 4; rg++) {
                int r = wm + i * 16 + gid + (rg >> 1) * 8;
                int c = wn + j * 8 + tig * 2 + (rg & 1);
                int gr = by * 128 + r;
                int gc = bx * 128 + c;
                g_x2[(size_t)gr * DMODEL + gc] = 2.f * (acc[i][j][rg] + pb[gc]);
            }
        }
    }
}

// ---------------- K5: LN2 + gate softmax + top2 routing ---------------------
__global__ void __launch_bounds__(128) k_gate(
    const float* __restrict__ n2w, const float* __restrict__ n2b,
    const float* __restrict__ gw)
{
    int t = blockIdx.x, tid = threadIdx.x;
    __shared__ float hs[DMODEL];
    __shared__ float red[64];
    const float* xr = g_x2 + (size_t)t * DMODEL;
    float v[4]; float s = 0.f, ss = 0.f;
    #pragma unroll
    for (int i = 0; i < 4; i++) {
        v[i] = xr[tid + i * 128];
        s += v[i]; ss += v[i] * v[i];
    }
    blockReduce2(s, ss, red);
    __shared__ float mu, rstd;
    if (tid == 0) {
        float m = s * (1.f / 512.f);
        mu = m; rstd = rsqrtf(ss * (1.f / 512.f) - m * m + 1e-5f);
    }
    __syncthreads();
    #pragma unroll
    for (int i = 0; i < 4; i++) {
        int d = tid + i * 128;
        float hv = (v[i] - mu) * rstd * n2w[d] + n2b[d];
        hs[d] = hv;
        g_hn[(size_t)t * DMODEL + d] = hv;
    }
    __syncthreads();
    int e = tid >> 4, ln = tid & 15;
    float p = 0.f;
    for (int d = ln; d < DMODEL; d += 16) p += hs[d] * gw[d * NEXP + e];
    #pragma unroll
    for (int o = 8; o; o >>= 1) p += __shfl_down_sync(0xffffffffu, p, o, 16);
    __shared__ float lg[NEXP];
    if (ln == 0) lg[e] = p;
    __syncthreads();
    if (tid == 0) {
        int i0 = 0; float b0 = lg[0];
        #pragma unroll
        for (int i = 1; i < NEXP; i++) if (lg[i] > b0) { b0 = lg[i]; i0 = i; }
        int i1 = -1; float b1 = -1e30f;
        #pragma unroll
        for (int i = 0; i < NEXP; i++) {
            if (i == i0) continue;
            if (lg[i] > b1) { b1 = lg[i]; i1 = i; }
        }
        float c0 = 1.f / (1.f + __expf(b1 - b0));
        int p0 = atomicAdd(&g_cnt[i0], 1);
        g_rows[i0 * SLOTS + p0] = t * 2;
        int p1 = atomicAdd(&g_cnt[i1], 1);
        g_rows[i1 * SLOTS + p1] = t * 2 + 1;
        g_conf[t * 2] = c0;
        g_conf[t * 2 + 1] = 1.f - c0;
    }
}

// ---------------- K6: grouped MoE GEMM 1 (hn @ w1, gelu) --------------------
__global__ void __launch_bounds__(256) k_moe1(
    const float* __restrict__ w1, const float* __restrict__ b1)
{
    int e = blockIdx.z, by = blockIdx.y, bx = blockIdx.x;
    int cnt = g_cnt[e];
    if (by * 128 >= cnt) return;
    __shared__ float As[2 * A_SZ], Bs[2 * B_SZ];
    __shared__ int arow[128], ent_s[128];
    int tid = threadIdx.x;
    if (tid < 128) {
        int rr = by * 128 + tid;
        int ent = (rr < cnt) ? g_rows[e * SLOTS + rr] : -1;
        ent_s[tid] = ent;
        arow[tid] = (ent >= 0) ? (ent >> 1) : -1;
    }
    __syncthreads();

    float acc[4][4][4] = {};
    gemm_3xtf32(g_hn, DMODEL, arow,
                w1 + (size_t)e * DMODEL * DFF + bx * 128, DFF, DMODEL, acc, As, Bs);

    int warp = tid >> 5, lane = tid & 31, gid = lane >> 2, tig = lane & 3;
    int wm = (warp & 1) * 64, wn = (warp >> 1) * 32;
    #pragma unroll
    for (int i = 0; i < 4; i++) {
        #pragma unroll
        for (int j = 0; j < 4; j++) {
            #pragma unroll
            for (int rg = 0; rg < 4; rg++) {
                int r = wm + i * 16 + gid + (rg >> 1) * 8;
                int ent = ent_s[r];
                if (ent < 0) continue;
                int gc = bx * 128 + wn + j * 8 + tig * 2 + (rg & 1);
                float vv = acc[i][j][rg] + b1[e * DFF + gc];
                vv = 0.5f * vv * (1.f + erff(vv * 0.70710678118654752f));
                g_hid[(size_t)ent * DFF + gc] = vv;
            }
        }
    }
}

// ---------------- K7: grouped MoE GEMM 2 (hid @ w2, *conf) ------------------
__global__ void __launch_bounds__(256) k_moe2(
    const float* __restrict__ w2, const float* __restrict__ b2)
{
    int e = blockIdx.z, by = blockIdx.y, bx = blockIdx.x;
    int cnt = g_cnt[e];
    if (by * 128 >= cnt) return;
    __shared__ float As[2 * A_SZ], Bs[2 * B_SZ];
    __shared__ int arow[128], ent_s[128];
    int tid = threadIdx.x;
    if (tid < 128) {
        int rr = by * 128 + tid;
        int ent = (rr < cnt) ? g_rows[e * SLOTS + rr] : -1;
        ent_s[tid] = ent;
        arow[tid] = ent;
    }
    __syncthreads();

    float acc[4][4][4] = {};
    gemm_3xtf32(g_hid, DFF, arow,
                w2 + (size_t)e * DFF * DMODEL + bx * 128, DMODEL, DFF, acc, As, Bs);

    int warp = tid >> 5, lane = tid & 31, gid = lane >> 2, tig = lane & 3;
    int wm = (warp & 1) * 64, wn = (warp >> 1) * 32;
    #pragma unroll
    for (int i = 0; i < 4; i++) {
        #pragma unroll
        for (int j = 0; j < 4; j++) {
            #pragma unroll
            for (int rg = 0; rg < 4; rg++) {
                int r = wm + i * 16 + gid + (rg >> 1) * 8;
                int ent = ent_s[r];
                if (ent < 0) continue;
                float cf = g_conf[ent];
                int gc = bx * 128 + wn + j * 8 + tig * 2 + (rg & 1);
                g_comb[(size_t)ent * DMODEL + gc] = cf * (acc[i][j][rg] + b2[e * DMODEL + gc]);
            }
        }
    }
}

// ---------------- K8: residual + LN(ln1) → out ------------------------------
__global__ void __launch_bounds__(256) k_final(
    const float* __restrict__ lw, const float* __restrict__ lb,
    float* __restrict__ out)
{
    int t = blockIdx.x, tid = threadIdx.x;
    const float* xr = g_x2 + (size_t)t * DMODEL;
    const float* c0 = g_comb + (size_t)(t * 2) * DMODEL;
    const float* c1 = g_comb + (size_t)(t * 2 + 1) * DMODEL;
    float v0 = xr[tid]       + c0[tid]       + c1[tid];
    float v1 = xr[tid + 256] + c0[tid + 256] + c1[tid + 256];
    float s = v0 + v1, ss = v0 * v0 + v1 * v1;
    __shared__ float red[64];
    blockReduce2(s, ss, red);
    __shared__ float mu, rstd;
    if (tid == 0) {
        float m = s * (1.f / 512.f);
        mu = m; rstd = rsqrtf(ss * (1.f / 512.f) - m * m + 1e-5f);
    }
    __syncthreads();
    out[(size_t)t * DMODEL + tid]       = (v0 - mu) * rstd * lw[tid]       + lb[tid];
    out[(size_t)t * DMODEL + tid + 256] = (v1 - mu) * rstd * lw[tid + 256] + lb[tid + 256];
}

// ---------------- launch -----------------------------------------------------
extern "C" void kernel_launch(void* const* d_in, const int* in_sizes, int n_in,
                              void* d_out, int out_size)
{
    const float* x1   = (const float*)d_in[0];
    const float* x2   = (const float*)d_in[1];
    const float* x3   = (const float*)d_in[2];
    const float* n1w  = (const float*)d_in[3];
    const float* n1b  = (const float*)d_in[4];
    const float* n2w  = (const float*)d_in[5];
    const float* n2b  = (const float*)d_in[6];
    const float* l1w  = (const float*)d_in[7];
    const float* l1b  = (const float*)d_in[8];
    const float* qw   = (const float*)d_in[9];
    const float* kvw  = (const float*)d_in[10];
    const float* pw   = (const float*)d_in[11];
    const float* pb   = (const float*)d_in[12];
    const float* gw   = (const float*)d_in[13];
    const float* ew1  = (const float*)d_in[14];
    const float* eb1  = (const float*)d_in[15];
    const float* ew2  = (const float*)d_in[16];
    const float* eb2  = (const float*)d_in[17];
    float* out = (float*)d_out;

    k_ln1<<<TOK, 256>>>(x1, x2, x3, n1w, n1b);
    { dim3 g(12, 48); k_qkv<<<g, 256>>>(qw, kvw); }
    { dim3 g(64, 12); k_attn<<<g, 128>>>(); }
    { dim3 g(4, 48);  k_proj<<<g, 256>>>(pw, pb); }
    k_gate<<<TOK, 128>>>(n2w, n2b, gw);
    { dim3 g(8, 96, 8); k_moe1<<<g, 256>>>(ew1, eb1); }
    { dim3 g(4, 96, 8); k_moe2<<<g, 256>>>(ew2, eb2); }
    k_final<<<TOK, 256>>>(l1w, l1b, out);
}